// round 3
// baseline (speedup 1.0000x reference)
#include <cuda_runtime.h>

// Problem constants
#define NPTS 100000
#define CIN  16
#define FOUT 16
#define BW   8
#define NDIM 3
#define NSEG 8192

// Pre-conv tiling: PN=32 points/CTA, duplicated-x smem layout
#define PN    32
#define T1    128
#define WSTR  36                      // words between w slots (c duplicated: 32 + 4 pad)
#define PSTR  362                     // words between point rows (10*36 + 2 pad)
#define XWORDS ((PN + 2) * PSTR)      // 34 * 362 = 12308 floats
#define SM_FLOATS (XWORDS + 2304 + 16)
#define SM_BYTES  (SM_FLOATS * 4)

// Device scratch (static allocation — no cudaMalloc allowed)
__device__ float g_seg[NDIM * NSEG * BW * FOUT];   // segment sums, 12.6 MB
__device__ float g_z  [NDIM * NSEG * BW * FOUT];   // post-conv output, 12.6 MB

// Packed fp32x2 FMA (Blackwell FFMA2 — PTX-only)
#define FMA2(acc, x2, w2) \
    asm("fma.rn.f32x2 %0, %1, %2, %0;" : "+l"(acc) : "l"(x2), "l"(w2))

// ---------------------------------------------------------------------------
// Kernel 0: zero the segment-sum scratch (must run every launch / graph replay)
// ---------------------------------------------------------------------------
__global__ void zero_seg_kernel() {
    const int total = NDIM * NSEG * BW * FOUT / 4;
    float4* p = reinterpret_cast<float4*>(g_seg);
    const float4 z = make_float4(0.f, 0.f, 0.f, 0.f);
    for (int i = blockIdx.x * blockDim.x + threadIdx.x; i < total;
         i += gridDim.x * blockDim.x)
        p[i] = z;
}

// ---------------------------------------------------------------------------
// Kernel 1: gather X[inv] -> 3x3 conv + relu -> atomic segment-sum
// grid: (NPTS/PN, NDIM), block: 128, 3 CTAs/SM
// smem x tile: [pt 0..33][wslot 0..9][c duplicated as {v,v} pairs]
//   word addr = pt*362 + wslot*36 + 2c   (8B aligned, conflict-free LDS.64)
// Each thread: 2 (point,w) outputs x 16 filters via FFMA2; x operand is a
// single LDS.64 of the pre-duplicated pair (no pack MOVs).
// ---------------------------------------------------------------------------
__global__ void __launch_bounds__(T1, 3)
pre_conv_kernel(const float* __restrict__ X, const int* __restrict__ inv,
                const int* __restrict__ index,
                const float* __restrict__ pre_w, const float* __restrict__ pre_b)
{
    extern __shared__ float sm[];
    float* xs = sm;                       // XWORDS
    float* ws = sm + XWORDS;              // 2304 = 3*3*16*16
    float* bs = ws + 2304;                // 16

    const int tid    = threadIdx.x;
    const int d      = blockIdx.y;
    const int bstart = blockIdx.x * PN;

    // Zero the x tile (pad words + halo/pad rows must be 0)
    {
        float4* xz = reinterpret_cast<float4*>(xs);
        const float4 z = make_float4(0.f, 0.f, 0.f, 0.f);
        for (int i = tid; i < XWORDS / 4; i += T1) xz[i] = z;
    }

    // Load weights + bias for this dim
    for (int i = tid; i < 2304; i += T1) ws[i] = pre_w[d * 2304 + i];
    if (tid < FOUT) bs[tid] = pre_b[d * FOUT + tid];
    __syncthreads();

    // Gather phase: interior rows only (pt 0..33 with halo; wslot 1..8)
    for (int r = tid; r < (PN + 2) * 10; r += T1) {
        const int pt = r / 10;
        const int wc = r - pt * 10;           // 0..9; 0 and 9 stay zero
        const int gp = bstart - 1 + pt;
        if (wc < 1 || wc > BW || gp < 0 || gp >= NPTS) continue;
        const int idx = inv[(d * NPTS + gp) * BW + (wc - 1)];
        const float4* xp = reinterpret_cast<const float4*>(X) + idx * 4;
        const float4 v0 = xp[0], v1 = xp[1], v2 = xp[2], v3 = xp[3];
        float2* dst = reinterpret_cast<float2*>(xs + pt * PSTR + wc * WSTR);
        dst[0]  = make_float2(v0.x, v0.x); dst[1]  = make_float2(v0.y, v0.y);
        dst[2]  = make_float2(v0.z, v0.z); dst[3]  = make_float2(v0.w, v0.w);
        dst[4]  = make_float2(v1.x, v1.x); dst[5]  = make_float2(v1.y, v1.y);
        dst[6]  = make_float2(v1.z, v1.z); dst[7]  = make_float2(v1.w, v1.w);
        dst[8]  = make_float2(v2.x, v2.x); dst[9]  = make_float2(v2.y, v2.y);
        dst[10] = make_float2(v2.z, v2.z); dst[11] = make_float2(v2.w, v2.w);
        dst[12] = make_float2(v3.x, v3.x); dst[13] = make_float2(v3.y, v3.y);
        dst[14] = make_float2(v3.z, v3.z); dst[15] = make_float2(v3.w, v3.w);
    }
    __syncthreads();

    const int w  = tid & 7;       // beam position
    const int p0 = tid >> 3;      // local point 0..15 (pair j adds 16)

    // 2 pairs x 16 filters as 8 packed f32x2 accumulators each
    unsigned long long acc[2][8];
#pragma unroll
    for (int j = 0; j < 2; ++j)
#pragma unroll
        for (int q = 0; q < 8; ++q) acc[j][q] = 0ull;

    const int JSTR = 16 * PSTR;   // 5792 words between j-pairs

#pragma unroll 1
    for (int a = 0; a < 3; ++a) {
#pragma unroll 1
        for (int b = 0; b < 3; ++b) {
            const unsigned long long* xb = reinterpret_cast<const unsigned long long*>(
                xs + (p0 + a) * PSTR + (w + b) * WSTR);
            const unsigned long long* xb1 = reinterpret_cast<const unsigned long long*>(
                xs + (p0 + a) * PSTR + (w + b) * WSTR + JSTR);
            const ulonglong2* wb =
                reinterpret_cast<const ulonglong2*>(ws + (a * 3 + b) * 256);
#pragma unroll
            for (int c = 0; c < CIN; ++c) {
                const unsigned long long x20 = xb[c];    // {x,x} duplicated
                const unsigned long long x21 = xb1[c];
                const ulonglong2 wA = wb[c * 4 + 0];     // filters 0..3
                const ulonglong2 wB = wb[c * 4 + 1];     // filters 4..7
                const ulonglong2 wC = wb[c * 4 + 2];     // filters 8..11
                const ulonglong2 wD = wb[c * 4 + 3];     // filters 12..15
                FMA2(acc[0][0], x20, wA.x); FMA2(acc[0][1], x20, wA.y);
                FMA2(acc[0][2], x20, wB.x); FMA2(acc[0][3], x20, wB.y);
                FMA2(acc[0][4], x20, wC.x); FMA2(acc[0][5], x20, wC.y);
                FMA2(acc[0][6], x20, wD.x); FMA2(acc[0][7], x20, wD.y);
                FMA2(acc[1][0], x21, wA.x); FMA2(acc[1][1], x21, wA.y);
                FMA2(acc[1][2], x21, wB.x); FMA2(acc[1][3], x21, wB.y);
                FMA2(acc[1][4], x21, wC.x); FMA2(acc[1][5], x21, wC.y);
                FMA2(acc[1][6], x21, wD.x); FMA2(acc[1][7], x21, wD.y);
            }
        }
    }

    // Epilogue: bias + relu + vectorized atomic segment sum
#pragma unroll
    for (int j = 0; j < 2; ++j) {
        const int gp = bstart + p0 + j * 16;
        if (gp >= NPTS) continue;
        const int seg = index[d * NPTS + gp];
        float* dstp = g_seg + ((d * NSEG + seg) * BW + w) * FOUT;
        float fv[16];
#pragma unroll
        for (int q = 0; q < 8; ++q) {
            float lo, hi;
            asm("mov.b64 {%0, %1}, %2;" : "=f"(lo), "=f"(hi) : "l"(acc[j][q]));
            fv[2 * q] = lo; fv[2 * q + 1] = hi;
        }
#pragma unroll
        for (int fg = 0; fg < 4; ++fg) {
            const float v0 = fmaxf(fv[fg * 4 + 0] + bs[fg * 4 + 0], 0.f);
            const float v1 = fmaxf(fv[fg * 4 + 1] + bs[fg * 4 + 1], 0.f);
            const float v2 = fmaxf(fv[fg * 4 + 2] + bs[fg * 4 + 2], 0.f);
            const float v3 = fmaxf(fv[fg * 4 + 3] + bs[fg * 4 + 3], 0.f);
            asm volatile("red.global.add.v4.f32 [%0], {%1,%2,%3,%4};"
                         :: "l"(dstp + fg * 4),
                            "f"(v0), "f"(v1), "f"(v2), "f"(v3)
                         : "memory");
        }
    }
}

// ---------------------------------------------------------------------------
// Kernel 2: post conv (3,1) + relu on g_seg -> g_z
// ---------------------------------------------------------------------------
__global__ void __launch_bounds__(256)
post_conv_kernel(const float* __restrict__ post_w, const float* __restrict__ post_b)
{
    __shared__ float ws[768];   // [a][c][f] = 3*16*16
    __shared__ float bs[16];
    const int tid = threadIdx.x;
    const int d   = blockIdx.y;
    for (int i = tid; i < 768; i += 256) ws[i] = post_w[d * 768 + i];
    if (tid < FOUT) bs[tid] = post_b[d * FOUT + tid];
    __syncthreads();

    const int gt = blockIdx.x * 256 + tid;    // 0 .. NSEG*BW-1
    const int s  = gt >> 3;
    const int w  = gt & 7;

    float acc[16];
#pragma unroll
    for (int f = 0; f < 16; ++f) acc[f] = 0.f;

#pragma unroll
    for (int a = 0; a < 3; ++a) {
        const int ss = s + a - 1;
        if (ss < 0 || ss >= NSEG) continue;
        const float4* src = reinterpret_cast<const float4*>(
            g_seg + ((d * NSEG + ss) * BW + w) * FOUT);
#pragma unroll
        for (int cg = 0; cg < 4; ++cg) {
            const float4 x4 = src[cg];
            const float* wr = ws + (a * 16 + cg * 4) * 16;
#pragma unroll
            for (int f = 0; f < 16; ++f) acc[f] += x4.x * wr[f];
#pragma unroll
            for (int f = 0; f < 16; ++f) acc[f] += x4.y * wr[16 + f];
#pragma unroll
            for (int f = 0; f < 16; ++f) acc[f] += x4.z * wr[32 + f];
#pragma unroll
            for (int f = 0; f < 16; ++f) acc[f] += x4.w * wr[48 + f];
        }
    }

    float4* dst = reinterpret_cast<float4*>(g_z + ((d * NSEG + s) * BW + w) * FOUT);
#pragma unroll
    for (int fg = 0; fg < 4; ++fg) {
        float4 v;
        v.x = fmaxf(acc[fg * 4 + 0] + bs[fg * 4 + 0], 0.f);
        v.y = fmaxf(acc[fg * 4 + 1] + bs[fg * 4 + 1], 0.f);
        v.z = fmaxf(acc[fg * 4 + 2] + bs[fg * 4 + 2], 0.f);
        v.w = fmaxf(acc[fg * 4 + 3] + bs[fg * 4 + 3], 0.f);
        dst[fg] = v;
    }
}

// ---------------------------------------------------------------------------
// Kernel 3: Y[n,w,:] = sum_d g_z[d, index[d,n], w, :]
// one thread per 16B; warp covers one n (512B fully coalesced)
// ---------------------------------------------------------------------------
__global__ void __launch_bounds__(256)
gather_out_kernel(const int* __restrict__ index, float* __restrict__ out)
{
    const int gt = blockIdx.x * 256 + threadIdx.x;   // 0 .. NPTS*BW*4-1
    if (gt >= NPTS * BW * 4) return;
    const int n   = gt >> 5;          // point
    const int rem = gt & 31;          // (w, fg)

    const int s0 = index[n];
    const int s1 = index[NPTS + n];
    const int s2 = index[2 * NPTS + n];

    const float4* b0 = reinterpret_cast<const float4*>(
        g_z + (size_t)s0 * (BW * FOUT)) + rem;
    const float4* b1 = reinterpret_cast<const float4*>(
        g_z + (size_t)(NSEG + s1) * (BW * FOUT)) + rem;
    const float4* b2 = reinterpret_cast<const float4*>(
        g_z + (size_t)(2 * NSEG + s2) * (BW * FOUT)) + rem;

    const float4 v0 = *b0;
    const float4 v1 = *b1;
    const float4 v2 = *b2;

    float4 r;
    r.x = v0.x + v1.x + v2.x;
    r.y = v0.y + v1.y + v2.y;
    r.z = v0.z + v1.z + v2.z;
    r.w = v0.w + v1.w + v2.w;
    reinterpret_cast<float4*>(out)[gt] = r;
}

// ---------------------------------------------------------------------------
extern "C" void kernel_launch(void* const* d_in, const int* in_sizes, int n_in,
                              void* d_out, int out_size)
{
    const float* X      = (const float*)d_in[0];
    const int*   inv    = (const int*)  d_in[1];
    const int*   index  = (const int*)  d_in[2];
    const float* pre_w  = (const float*)d_in[3];
    const float* pre_b  = (const float*)d_in[4];
    const float* post_w = (const float*)d_in[5];
    const float* post_b = (const float*)d_in[6];
    float*       out    = (float*)      d_out;

    cudaFuncSetAttribute((const void*)pre_conv_kernel,
                         cudaFuncAttributeMaxDynamicSharedMemorySize, SM_BYTES);

    zero_seg_kernel<<<2048, 256>>>();

    dim3 g1(NPTS / PN, NDIM);
    pre_conv_kernel<<<g1, T1, SM_BYTES>>>(X, inv, index, pre_w, pre_b);

    dim3 g2(NSEG * BW / 256, NDIM);
    post_conv_kernel<<<g2, 256>>>(post_w, post_b);

    gather_out_kernel<<<(NPTS * BW * 4 + 255) / 256, 256>>>(index, out);
}

// round 6
// speedup vs baseline: 1.9771x; 1.9771x over previous
#include <cuda_runtime.h>
#include <cstdint>

// Problem constants
#define NPTS 100000
#define CIN  16
#define FOUT 16
#define BW   8
#define NDIM 3
#define NSEG 8192

// Pre-conv (tf32 mma.sync) tiling
#define PN    32                  // points per CTA -> 256 output rows
#define T1    256
#define CSTR  24                  // words per tile row (16 data + 8 pad, bank-magic)
#define NROW  (34 * 10)           // (PN+2 pt-halo) x 10 w-slots
#define XS_WORDS (NROW * CSTR)    // 8160
#define WB_WORDS (144 * CSTR)     // 3456 (9 taps x 16 filters rows)
#define BS_OFF   (XS_WORDS + WB_WORDS)        // 11616
#define SM_WORDS (BS_OFF + 16)                // 11632
#define SM_BYTES (SM_WORDS * 4)               // 46528 (< 48KB default)

// channel permutation: pairs (c, c+4) adjacent -> one LDS.64 per fragment half
__host__ __device__ __forceinline__ int perm_c(int c) {
    const int g = c >> 3, cc = c & 7;
    return g * 8 + (cc & 3) * 2 + (cc >> 2);
}

__device__ __forceinline__ uint32_t cvt_tf32(float v) {
    uint32_t u;
    asm("cvt.rna.tf32.f32 %0, %1;" : "=r"(u) : "f"(v));
    return u;
}

#define MMA_TF32(acc, a0, a1, a2, a3, b0, b1)                                  \
    asm("mma.sync.aligned.m16n8k8.row.col.f32.tf32.tf32.f32 "                  \
        "{%0,%1,%2,%3},{%4,%5,%6,%7},{%8,%9},{%0,%1,%2,%3};"                   \
        : "+f"(acc[0]), "+f"(acc[1]), "+f"(acc[2]), "+f"(acc[3])               \
        : "r"(a0), "r"(a1), "r"(a2), "r"(a3), "r"(b0), "r"(b1))

// Device scratch (static allocation — no cudaMalloc allowed)
__device__ float g_seg[NDIM * NSEG * BW * FOUT];   // segment sums, 12.6 MB
__device__ float g_z  [NDIM * NSEG * BW * FOUT];   // post-conv output, 12.6 MB

// ---------------------------------------------------------------------------
// Kernel 0: zero the segment-sum scratch
// ---------------------------------------------------------------------------
__global__ void zero_seg_kernel() {
    const int total = NDIM * NSEG * BW * FOUT / 4;
    float4* p = reinterpret_cast<float4*>(g_seg);
    const float4 z = make_float4(0.f, 0.f, 0.f, 0.f);
    for (int i = blockIdx.x * blockDim.x + threadIdx.x; i < total;
         i += gridDim.x * blockDim.x)
        p[i] = z;
}

// ---------------------------------------------------------------------------
// Kernel 1: gather X[inv] -> tf32 mma.sync 3x3 conv -> relu -> atomic seg-sum
// grid (3125, 3), block 256 (8 warps). Warp w: output rows [32w, 32w+32).
// smem x tile: row = pt_h*10 + wslot, CSTR=24 words, channels pair-permuted.
// GEMM: M=256 rows, N=16 filters, K=144 (9 taps x 16 ch), k-step 8.
// ---------------------------------------------------------------------------
__global__ void __launch_bounds__(T1)
pre_conv_mma_kernel(const float* __restrict__ X, const int* __restrict__ inv,
                    const int* __restrict__ index,
                    const float* __restrict__ pre_w, const float* __restrict__ pre_b)
{
    extern __shared__ float sm[];
    float* xs = sm;                 // gathered tile (tf32 bits)
    float* wb = sm + XS_WORDS;      // weights: row = tap*16+f, word = perm(c)
    float* bs = sm + BS_OFF;        // bias

    const int tid    = threadIdx.x;
    const int wid    = tid >> 5;
    const int lane   = tid & 31;
    const int q      = lane & 3;    // fragment k-quad
    const int lr     = lane >> 2;   // fragment row / n index (0..7)
    const int d      = blockIdx.y;
    const int bstart = blockIdx.x * PN;

    // Zero the x tile (halo + pad slots must be 0)
    {
        float4* xz = reinterpret_cast<float4*>(xs);
        const float4 z = make_float4(0.f, 0.f, 0.f, 0.f);
        for (int i = tid; i < XS_WORDS / 4; i += T1) xz[i] = z;
    }
    // Weights -> tf32, permuted
    for (int i = tid; i < 2304; i += T1) {
        const int tap = i >> 8;          // a*3+b
        const int c   = (i >> 4) & 15;
        const int f   = i & 15;
        wb[(tap * 16 + f) * CSTR + perm_c(c)] =
            __uint_as_float(cvt_tf32(pre_w[d * 2304 + i]));
    }
    if (tid < FOUT) bs[tid] = pre_b[d * FOUT + tid];
    __syncthreads();

    // Gather: 272 (pt_h, w) rows; interleaved-pair tf32 store (4x STS.128)
    for (int r = tid; r < 34 * 8; r += T1) {
        const int pt = r >> 3;
        const int w  = r & 7;
        const int gp = bstart - 1 + pt;
        if ((unsigned)gp >= NPTS) continue;
        const int idx = inv[(d * NPTS + gp) * BW + w];
        const float4* xp = reinterpret_cast<const float4*>(X) + idx * 4;
        const float4 v0 = xp[0], v1 = xp[1], v2 = xp[2], v3 = xp[3];
        uint4* dst = reinterpret_cast<uint4*>(xs + (pt * 10 + (w + 1)) * CSTR);
        uint4 o;
        o.x = cvt_tf32(v0.x); o.y = cvt_tf32(v1.x);
        o.z = cvt_tf32(v0.y); o.w = cvt_tf32(v1.y); dst[0] = o;
        o.x = cvt_tf32(v0.z); o.y = cvt_tf32(v1.z);
        o.z = cvt_tf32(v0.w); o.w = cvt_tf32(v1.w); dst[1] = o;
        o.x = cvt_tf32(v2.x); o.y = cvt_tf32(v3.x);
        o.z = cvt_tf32(v2.y); o.w = cvt_tf32(v3.y); dst[2] = o;
        o.x = cvt_tf32(v2.z); o.y = cvt_tf32(v3.z);
        o.z = cvt_tf32(v2.w); o.w = cvt_tf32(v3.w); dst[3] = o;
    }
    __syncthreads();

    // A-fragment row bases: j = 0..3 -> rows wid*32 + j*8 + lr
    // (pt = wid*4 + j, w = lr); word = (pt*10 + w)*CSTR + 2q (+ tap offset)
    int abase[4];
#pragma unroll
    for (int j = 0; j < 4; ++j)
        abase[j] = ((wid * 4 + j) * 10 + lr) * CSTR + 2 * q;

    float acc[2][2][4];
#pragma unroll
    for (int mt = 0; mt < 2; ++mt)
#pragma unroll
        for (int nt = 0; nt < 2; ++nt)
#pragma unroll
            for (int i = 0; i < 4; ++i) acc[mt][nt][i] = 0.f;

#pragma unroll
    for (int ks = 0; ks < 18; ++ks) {
        const int tap   = ks >> 1;               // a*3+b
        const int chalf = ks & 1;
        const int a     = tap / 3, b = tap - 3 * a;
        const int toff  = (a * 10 + b) * CSTR + chalf * 8;

        // B fragments (one LDS.64 per n-tile)
        const uint2 bf0 = *reinterpret_cast<const uint2*>(
            wb + (tap * 16 + lr) * CSTR + chalf * 8 + 2 * q);
        const uint2 bf1 = *reinterpret_cast<const uint2*>(
            wb + (tap * 16 + 8 + lr) * CSTR + chalf * 8 + 2 * q);
        // A fragments (one LDS.64 per 8-row group)
        const uint2 a0 = *reinterpret_cast<const uint2*>(xs + abase[0] + toff);
        const uint2 a1 = *reinterpret_cast<const uint2*>(xs + abase[1] + toff);
        const uint2 a2 = *reinterpret_cast<const uint2*>(xs + abase[2] + toff);
        const uint2 a3 = *reinterpret_cast<const uint2*>(xs + abase[3] + toff);

        MMA_TF32(acc[0][0], a0.x, a1.x, a0.y, a1.y, bf0.x, bf0.y);
        MMA_TF32(acc[0][1], a0.x, a1.x, a0.y, a1.y, bf1.x, bf1.y);
        MMA_TF32(acc[1][0], a2.x, a3.x, a2.y, a3.y, bf0.x, bf0.y);
        MMA_TF32(acc[1][1], a2.x, a3.x, a2.y, a3.y, bf1.x, bf1.y);
    }

    // Epilogue: bias + relu + red.v2 into g_seg.
    // m-tile mt: low rows pt = wid*4 + 2mt (w = lr), high rows pt+1.
#pragma unroll
    for (int mt = 0; mt < 2; ++mt) {
        const int pt_lo = wid * 4 + mt * 2;
        const int seg_lo = index[d * NPTS + bstart + pt_lo];
        const int seg_hi = index[d * NPTS + bstart + pt_lo + 1];
        float* base_lo = g_seg + ((d * NSEG + seg_lo) * BW + lr) * FOUT;
        float* base_hi = g_seg + ((d * NSEG + seg_hi) * BW + lr) * FOUT;
#pragma unroll
        for (int nt = 0; nt < 2; ++nt) {
            const int col = nt * 8 + 2 * q;
            const float b0v = bs[col], b1v = bs[col + 1];
            const float v0 = fmaxf(acc[mt][nt][0] + b0v, 0.f);
            const float v1 = fmaxf(acc[mt][nt][1] + b1v, 0.f);
            const float v2 = fmaxf(acc[mt][nt][2] + b0v, 0.f);
            const float v3 = fmaxf(acc[mt][nt][3] + b1v, 0.f);
            asm volatile("red.global.add.v2.f32 [%0], {%1,%2};"
                         :: "l"(base_lo + col), "f"(v0), "f"(v1) : "memory");
            asm volatile("red.global.add.v2.f32 [%0], {%1,%2};"
                         :: "l"(base_hi + col), "f"(v2), "f"(v3) : "memory");
        }
    }
}

// ---------------------------------------------------------------------------
// Kernel 2: post conv (3,1) + relu on g_seg -> g_z
// ---------------------------------------------------------------------------
__global__ void __launch_bounds__(256)
post_conv_kernel(const float* __restrict__ post_w, const float* __restrict__ post_b)
{
    __shared__ float ws[768];
    __shared__ float bs[16];
    const int tid = threadIdx.x;
    const int d   = blockIdx.y;
    for (int i = tid; i < 768; i += 256) ws[i] = post_w[d * 768 + i];
    if (tid < FOUT) bs[tid] = post_b[d * FOUT + tid];
    __syncthreads();

    const int gt = blockIdx.x * 256 + tid;
    const int s  = gt >> 3;
    const int w  = gt & 7;

    float acc[16];
#pragma unroll
    for (int f = 0; f < 16; ++f) acc[f] = 0.f;

#pragma unroll
    for (int a = 0; a < 3; ++a) {
        const int ss = s + a - 1;
        if (ss < 0 || ss >= NSEG) continue;
        const float4* src = reinterpret_cast<const float4*>(
            g_seg + ((d * NSEG + ss) * BW + w) * FOUT);
#pragma unroll
        for (int cg = 0; cg < 4; ++cg) {
            const float4 x4 = src[cg];
            const float* wr = ws + (a * 16 + cg * 4) * 16;
#pragma unroll
            for (int f = 0; f < 16; ++f) acc[f] += x4.x * wr[f];
#pragma unroll
            for (int f = 0; f < 16; ++f) acc[f] += x4.y * wr[16 + f];
#pragma unroll
            for (int f = 0; f < 16; ++f) acc[f] += x4.z * wr[32 + f];
#pragma unroll
            for (int f = 0; f < 16; ++f) acc[f] += x4.w * wr[48 + f];
        }
    }

    float4* dst = reinterpret_cast<float4*>(g_z + ((d * NSEG + s) * BW + w) * FOUT);
#pragma unroll
    for (int fg = 0; fg < 4; ++fg) {
        float4 v;
        v.x = fmaxf(acc[fg * 4 + 0] + bs[fg * 4 + 0], 0.f);
        v.y = fmaxf(acc[fg * 4 + 1] + bs[fg * 4 + 1], 0.f);
        v.z = fmaxf(acc[fg * 4 + 2] + bs[fg * 4 + 2], 0.f);
        v.w = fmaxf(acc[fg * 4 + 3] + bs[fg * 4 + 3], 0.f);
        dst[fg] = v;
    }
}

// ---------------------------------------------------------------------------
// Kernel 3: Y[n,w,:] = sum_d g_z[d, index[d,n], w, :]
// ---------------------------------------------------------------------------
__global__ void __launch_bounds__(256)
gather_out_kernel(const int* __restrict__ index, float* __restrict__ out)
{
    const int gt = blockIdx.x * 256 + threadIdx.x;
    if (gt >= NPTS * BW * 4) return;
    const int n   = gt >> 5;
    const int rem = gt & 31;

    const int s0 = index[n];
    const int s1 = index[NPTS + n];
    const int s2 = index[2 * NPTS + n];

    const float4* b0 = reinterpret_cast<const float4*>(
        g_z + (size_t)s0 * (BW * FOUT)) + rem;
    const float4* b1 = reinterpret_cast<const float4*>(
        g_z + (size_t)(NSEG + s1) * (BW * FOUT)) + rem;
    const float4* b2 = reinterpret_cast<const float4*>(
        g_z + (size_t)(2 * NSEG + s2) * (BW * FOUT)) + rem;

    const float4 v0 = *b0;
    const float4 v1 = *b1;
    const float4 v2 = *b2;

    float4 r;
    r.x = v0.x + v1.x + v2.x;
    r.y = v0.y + v1.y + v2.y;
    r.z = v0.z + v1.z + v2.z;
    r.w = v0.w + v1.w + v2.w;
    reinterpret_cast<float4*>(out)[gt] = r;
}

// ---------------------------------------------------------------------------
extern "C" void kernel_launch(void* const* d_in, const int* in_sizes, int n_in,
                              void* d_out, int out_size)
{
    const float* X      = (const float*)d_in[0];
    const int*   inv    = (const int*)  d_in[1];
    const int*   index  = (const int*)  d_in[2];
    const float* pre_w  = (const float*)d_in[3];
    const float* pre_b  = (const float*)d_in[4];
    const float* post_w = (const float*)d_in[5];
    const float* post_b = (const float*)d_in[6];
    float*       out    = (float*)      d_out;

    zero_seg_kernel<<<2048, 256>>>();

    dim3 g1(NPTS / PN, NDIM);
    pre_conv_mma_kernel<<<g1, T1, SM_BYTES>>>(X, inv, index, pre_w, pre_b);

    dim3 g2(NSEG * BW / 256, NDIM);
    post_conv_kernel<<<g2, 256>>>(post_w, post_b);

    gather_out_kernel<<<(NPTS * BW * 4 + 255) / 256, 256>>>(index, out);
}

// round 7
// speedup vs baseline: 2.4901x; 1.2594x over previous
#include <cuda_runtime.h>
#include <cstdint>

// Problem constants
#define NPTS 100000
#define CIN  16
#define FOUT 16
#define BW   8
#define NDIM 3
#define NSEG 8192

// Pre-conv (bf16 mma.sync m16n8k16) tiling
#define PN    64                  // points per CTA -> 512 output rows
#define T1    256                 // 8 warps; warp covers 64 rows (4 m16 tiles)
#define NB    1563                // ceil(100000/64)
#define XS_WORDS (66 * 10 * 8)    // 5280: (PN+2 pt-halo) x 10 w-slots x 8 words
#define WB_WORDS (144 * 8)        // 1152: 9 taps x 16 filter rows x 8 words

__device__ __forceinline__ uint32_t pack_bf16x2(float lo, float hi) {
    uint32_t r;
    asm("cvt.rn.bf16x2.f32 %0, %1, %2;" : "=r"(r) : "f"(hi), "f"(lo));
    return r;
}

#define MMA_BF16(acc, a0, a1, a2, a3, b0, b1)                                  \
    asm("mma.sync.aligned.m16n8k16.row.col.f32.bf16.bf16.f32 "                 \
        "{%0,%1,%2,%3},{%4,%5,%6,%7},{%8,%9},{%0,%1,%2,%3};"                   \
        : "+f"(acc[0]), "+f"(acc[1]), "+f"(acc[2]), "+f"(acc[3])               \
        : "r"(a0), "r"(a1), "r"(a2), "r"(a3), "r"(b0), "r"(b1))

// Device scratch (static allocation — no cudaMalloc allowed)
__device__ float g_seg[NDIM * NSEG * BW * FOUT];   // segment sums, 12.6 MB
__device__ float g_z  [NDIM * NSEG * BW * FOUT];   // post-conv output, 12.6 MB

// ---------------------------------------------------------------------------
// Kernel 0: zero the segment-sum scratch
// ---------------------------------------------------------------------------
__global__ void zero_seg_kernel() {
    const int total = NDIM * NSEG * BW * FOUT / 4;
    float4* p = reinterpret_cast<float4*>(g_seg);
    const float4 z = make_float4(0.f, 0.f, 0.f, 0.f);
    for (int i = blockIdx.x * blockDim.x + threadIdx.x; i < total;
         i += gridDim.x * blockDim.x)
        p[i] = z;
}

// ---------------------------------------------------------------------------
// Kernel 1: gather X[inv] -> bf16 mma 3x3 conv -> relu -> atomic seg-sum
// grid (1563, 3), block 256 (8 warps). Warp wid: output rows [64wid, 64wid+64).
// smem x tile: row = pt_h*10 + wslot, 8 words/row (32B bf16), channel words
// pair-permuted: word j = (c_j, c_{j+1}) for even j, (c_{j+7}, c_{j+8}) odd j.
// -> every mma fragment pair (k, k+8) is one LDS.64; CSTR=8 conflict-free.
// GEMM: M=512 rows, N=16 filters, K=144 as 9 taps x k16 (implicit im2col).
// ---------------------------------------------------------------------------
__global__ void __launch_bounds__(T1)
pre_conv_mma_kernel(const float* __restrict__ X, const int* __restrict__ inv,
                    const int* __restrict__ index,
                    const float* __restrict__ pre_w, const float* __restrict__ pre_b)
{
    __shared__ uint32_t xs[XS_WORDS];
    __shared__ uint32_t wb[WB_WORDS];
    __shared__ float    bs[16];

    const int tid    = threadIdx.x;
    const int wid    = tid >> 5;
    const int lane   = tid & 31;
    const int q      = lane & 3;    // fragment k-quad
    const int lr     = lane >> 2;   // fragment row / n index (0..7)
    const int d      = blockIdx.y;
    const int bstart = blockIdx.x * PN;

    // Zero the x tile (halo + pad slots must be 0)
    {
        uint4* xz = reinterpret_cast<uint4*>(xs);
        const uint4 z = make_uint4(0u, 0u, 0u, 0u);
        for (int i = tid; i < XS_WORDS / 4; i += T1) xz[i] = z;
    }
    // Weights -> bf16 pairs, permuted. pre_w layout [tap][c][f].
    for (int i = tid; i < 1152; i += T1) {
        const int tap = i >> 7;
        const int rem = i & 127;
        const int f   = rem >> 3;
        const int j   = rem & 7;
        const int c   = (j & 1) ? (j + 7) : j;
        const int base = d * 2304 + tap * 256;
        const float wlo = pre_w[base + c * 16 + f];
        const float whi = pre_w[base + (c + 1) * 16 + f];
        wb[(tap * 16 + f) * 8 + j] = pack_bf16x2(wlo, whi);
    }
    if (tid < FOUT) bs[tid] = pre_b[d * FOUT + tid];
    __syncthreads();

    // Gather: 528 (pt_h, w) rows; convert to permuted bf16, 2x STS.128
    for (int r = tid; r < 66 * 8; r += T1) {
        const int pt = r >> 3;
        const int w  = r & 7;
        const int gp = bstart - 1 + pt;
        if ((unsigned)gp >= NPTS) continue;
        const int idx = inv[(d * NPTS + gp) * BW + w];
        const float4* xp = reinterpret_cast<const float4*>(X) + idx * 4;
        const float4 v0 = xp[0], v1 = xp[1], v2 = xp[2], v3 = xp[3];
        uint4 o0, o1;
        o0.x = pack_bf16x2(v0.x, v0.y);   // (c0,c1)
        o0.y = pack_bf16x2(v2.x, v2.y);   // (c8,c9)
        o0.z = pack_bf16x2(v0.z, v0.w);   // (c2,c3)
        o0.w = pack_bf16x2(v2.z, v2.w);   // (c10,c11)
        o1.x = pack_bf16x2(v1.x, v1.y);   // (c4,c5)
        o1.y = pack_bf16x2(v3.x, v3.y);   // (c12,c13)
        o1.z = pack_bf16x2(v1.z, v1.w);   // (c6,c7)
        o1.w = pack_bf16x2(v3.z, v3.w);   // (c14,c15)
        uint4* dst = reinterpret_cast<uint4*>(xs + (pt * 10 + w + 1) * 8);
        dst[0] = o0; dst[1] = o1;
    }
    __syncthreads();

    // A-fragment bases: m-tile mt covers rows wid*64 + mt*16 + {lr, lr+8}
    // -> (pt = wid*8 + mt*2 (+1), w = lr); smem addr adds (a*10+b)*8 per tap.
    int base_lo[4], base_hi[4];
#pragma unroll
    for (int mt = 0; mt < 4; ++mt) {
        const int ptl = wid * 8 + mt * 2;
        base_lo[mt] = (ptl * 10 + lr) * 8 + 2 * q;
        base_hi[mt] = base_lo[mt] + 80;
    }

    float acc[4][2][4];
#pragma unroll
    for (int mt = 0; mt < 4; ++mt)
#pragma unroll
        for (int nt = 0; nt < 2; ++nt)
#pragma unroll
            for (int i = 0; i < 4; ++i) acc[mt][nt][i] = 0.f;

#pragma unroll
    for (int a = 0; a < 3; ++a) {
#pragma unroll
        for (int b = 0; b < 3; ++b) {
            const int tap  = a * 3 + b;
            const int toff = (a * 10 + b) * 8;
            // B fragments: one LDS.64 per n-tile
            const uint2 bf0 = *reinterpret_cast<const uint2*>(
                wb + (tap * 16 + lr) * 8 + 2 * q);
            const uint2 bf1 = *reinterpret_cast<const uint2*>(
                wb + (tap * 16 + 8 + lr) * 8 + 2 * q);
#pragma unroll
            for (int mt = 0; mt < 4; ++mt) {
                const uint2 alo = *reinterpret_cast<const uint2*>(
                    xs + base_lo[mt] + toff);          // a0 (k..), a2 (k+8..)
                const uint2 ahi = *reinterpret_cast<const uint2*>(
                    xs + base_hi[mt] + toff);          // a1, a3
                MMA_BF16(acc[mt][0], alo.x, ahi.x, alo.y, ahi.y, bf0.x, bf0.y);
                MMA_BF16(acc[mt][1], alo.x, ahi.x, alo.y, ahi.y, bf1.x, bf1.y);
            }
        }
    }

    // Epilogue: bias + relu + red.v2 into g_seg
#pragma unroll
    for (int mt = 0; mt < 4; ++mt) {
        const int ptl   = wid * 8 + mt * 2;
        const int gp_lo = bstart + ptl;
        const int gp_hi = gp_lo + 1;
        float* base_l = nullptr;
        float* base_h = nullptr;
        if (gp_lo < NPTS) {
            const int seg = index[d * NPTS + gp_lo];
            base_l = g_seg + ((d * NSEG + seg) * BW + lr) * FOUT;
        }
        if (gp_hi < NPTS) {
            const int seg = index[d * NPTS + gp_hi];
            base_h = g_seg + ((d * NSEG + seg) * BW + lr) * FOUT;
        }
#pragma unroll
        for (int nt = 0; nt < 2; ++nt) {
            const int col = nt * 8 + 2 * q;
            const float b0v = bs[col], b1v = bs[col + 1];
            if (base_l) {
                const float v0 = fmaxf(acc[mt][nt][0] + b0v, 0.f);
                const float v1 = fmaxf(acc[mt][nt][1] + b1v, 0.f);
                asm volatile("red.global.add.v2.f32 [%0], {%1,%2};"
                             :: "l"(base_l + col), "f"(v0), "f"(v1) : "memory");
            }
            if (base_h) {
                const float v2 = fmaxf(acc[mt][nt][2] + b0v, 0.f);
                const float v3 = fmaxf(acc[mt][nt][3] + b1v, 0.f);
                asm volatile("red.global.add.v2.f32 [%0], {%1,%2};"
                             :: "l"(base_h + col), "f"(v2), "f"(v3) : "memory");
            }
        }
    }
}

// ---------------------------------------------------------------------------
// Kernel 2: post conv (3,1) + relu on g_seg -> g_z
// ---------------------------------------------------------------------------
__global__ void __launch_bounds__(256)
post_conv_kernel(const float* __restrict__ post_w, const float* __restrict__ post_b)
{
    __shared__ float ws[768];
    __shared__ float bs[16];
    const int tid = threadIdx.x;
    const int d   = blockIdx.y;
    for (int i = tid; i < 768; i += 256) ws[i] = post_w[d * 768 + i];
    if (tid < FOUT) bs[tid] = post_b[d * FOUT + tid];
    __syncthreads();

    const int gt = blockIdx.x * 256 + tid;
    const int s  = gt >> 3;
    const int w  = gt & 7;

    float acc[16];
#pragma unroll
    for (int f = 0; f < 16; ++f) acc[f] = 0.f;

#pragma unroll
    for (int a = 0; a < 3; ++a) {
        const int ss = s + a - 1;
        if (ss < 0 || ss >= NSEG) continue;
        const float4* src = reinterpret_cast<const float4*>(
            g_seg + ((d * NSEG + ss) * BW + w) * FOUT);
#pragma unroll
        for (int cg = 0; cg < 4; ++cg) {
            const float4 x4 = src[cg];
            const float* wr = ws + (a * 16 + cg * 4) * 16;
#pragma unroll
            for (int f = 0; f < 16; ++f) acc[f] += x4.x * wr[f];
#pragma unroll
            for (int f = 0; f < 16; ++f) acc[f] += x4.y * wr[16 + f];
#pragma unroll
            for (int f = 0; f < 16; ++f) acc[f] += x4.z * wr[32 + f];
#pragma unroll
            for (int f = 0; f < 16; ++f) acc[f] += x4.w * wr[48 + f];
        }
    }

    float4* dst = reinterpret_cast<float4*>(g_z + ((d * NSEG + s) * BW + w) * FOUT);
#pragma unroll
    for (int fg = 0; fg < 4; ++fg) {
        float4 v;
        v.x = fmaxf(acc[fg * 4 + 0] + bs[fg * 4 + 0], 0.f);
        v.y = fmaxf(acc[fg * 4 + 1] + bs[fg * 4 + 1], 0.f);
        v.z = fmaxf(acc[fg * 4 + 2] + bs[fg * 4 + 2], 0.f);
        v.w = fmaxf(acc[fg * 4 + 3] + bs[fg * 4 + 3], 0.f);
        dst[fg] = v;
    }
}

// ---------------------------------------------------------------------------
// Kernel 3: Y[n,w,:] = sum_d g_z[d, index[d,n], w, :]
// ---------------------------------------------------------------------------
__global__ void __launch_bounds__(256)
gather_out_kernel(const int* __restrict__ index, float* __restrict__ out)
{
    const int gt = blockIdx.x * 256 + threadIdx.x;
    if (gt >= NPTS * BW * 4) return;
    const int n   = gt >> 5;
    const int rem = gt & 31;

    const int s0 = index[n];
    const int s1 = index[NPTS + n];
    const int s2 = index[2 * NPTS + n];

    const float4* b0 = reinterpret_cast<const float4*>(
        g_z + (size_t)s0 * (BW * FOUT)) + rem;
    const float4* b1 = reinterpret_cast<const float4*>(
        g_z + (size_t)(NSEG + s1) * (BW * FOUT)) + rem;
    const float4* b2 = reinterpret_cast<const float4*>(
        g_z + (size_t)(2 * NSEG + s2) * (BW * FOUT)) + rem;

    const float4 v0 = *b0;
    const float4 v1 = *b1;
    const float4 v2 = *b2;

    float4 r;
    r.x = v0.x + v1.x + v2.x;
    r.y = v0.y + v1.y + v2.y;
    r.z = v0.z + v1.z + v2.z;
    r.w = v0.w + v1.w + v2.w;
    reinterpret_cast<float4*>(out)[gt] = r;
}

// ---------------------------------------------------------------------------
extern "C" void kernel_launch(void* const* d_in, const int* in_sizes, int n_in,
                              void* d_out, int out_size)
{
    const float* X      = (const float*)d_in[0];
    const int*   inv    = (const int*)  d_in[1];
    const int*   index  = (const int*)  d_in[2];
    const float* pre_w  = (const float*)d_in[3];
    const float* pre_b  = (const float*)d_in[4];
    const float* post_w = (const float*)d_in[5];
    const float* post_b = (const float*)d_in[6];
    float*       out    = (float*)      d_out;

    zero_seg_kernel<<<2048, 256>>>();

    dim3 g1(NB, NDIM);
    pre_conv_mma_kernel<<<g1, T1>>>(X, inv, index, pre_w, pre_b);

    dim3 g2(NSEG * BW / 256, NDIM);
    post_conv_kernel<<<g2, 256>>>(post_w, post_b);

    gather_out_kernel<<<(NPTS * BW * 4 + 255) / 256, 256>>>(index, out);
}

// round 8
// speedup vs baseline: 2.5594x; 1.0279x over previous
#include <cuda_runtime.h>
#include <cstdint>

// Problem constants
#define NPTS 100000
#define CIN  16
#define FOUT 16
#define BW   8
#define NDIM 3
#define NSEG 8192

// Pre-conv (fp16 mma.sync m16n8k16) tiling
#define PN    32                  // points per CTA -> 256 output rows
#define T1    256                 // 8 warps; warp covers 32 rows (2 m16 tiles)
#define NB    (NPTS / PN)         // 3125
#define XS_WORDS (34 * 10 * 8)    // 2720: (PN+2 pt-halo) x 10 w-slots x 8 words
#define WB_WORDS (144 * 8)        // 1152: 9 taps x 16 filter rows x 8 words

__device__ __forceinline__ uint32_t pack_f16x2(float lo, float hi) {
    uint32_t r;
    asm("cvt.rn.f16x2.f32 %0, %1, %2;" : "=r"(r) : "f"(hi), "f"(lo));
    return r;
}

#define MMA_F16(acc, a0, a1, a2, a3, b0, b1)                                   \
    asm("mma.sync.aligned.m16n8k16.row.col.f32.f16.f16.f32 "                   \
        "{%0,%1,%2,%3},{%4,%5,%6,%7},{%8,%9},{%0,%1,%2,%3};"                   \
        : "+f"(acc[0]), "+f"(acc[1]), "+f"(acc[2]), "+f"(acc[3])               \
        : "r"(a0), "r"(a1), "r"(a2), "r"(a3), "r"(b0), "r"(b1))

// Device scratch (static allocation — no cudaMalloc allowed)
__device__ float g_seg[NDIM * NSEG * BW * FOUT];   // segment sums, 12.6 MB
__device__ float g_z  [NDIM * NSEG * BW * FOUT];   // post-conv output, 12.6 MB

// ---------------------------------------------------------------------------
// Kernel 0: zero the segment-sum scratch
// ---------------------------------------------------------------------------
__global__ void zero_seg_kernel() {
    const int total = NDIM * NSEG * BW * FOUT / 4;
    float4* p = reinterpret_cast<float4*>(g_seg);
    const float4 z = make_float4(0.f, 0.f, 0.f, 0.f);
    for (int i = blockIdx.x * blockDim.x + threadIdx.x; i < total;
         i += gridDim.x * blockDim.x)
        p[i] = z;
}

// ---------------------------------------------------------------------------
// Kernel 1: gather X[inv] -> fp16 mma 3x3 conv -> relu -> atomic seg-sum
// grid (3125, 3), block 256 (8 warps). Warp wid: output rows [32wid, 32wid+32).
// smem x tile: row = pt_h*10 + wslot, 8 words/row (32B fp16), channel words
// pair-permuted: word j = (c_j, c_{j+1}) for even j, (c_{j+7}, c_{j+8}) odd j.
// -> every mma fragment pair (k, k+8) is one LDS.64; 8-word rows conflict-free.
// GEMM: M=256 rows, N=16 filters, K=144 as 9 taps x k16 (implicit im2col).
// ---------------------------------------------------------------------------
__global__ void __launch_bounds__(T1)
pre_conv_mma_kernel(const float* __restrict__ X, const int* __restrict__ inv,
                    const int* __restrict__ index,
                    const float* __restrict__ pre_w, const float* __restrict__ pre_b)
{
    __shared__ uint32_t xs[XS_WORDS];
    __shared__ uint32_t wb[WB_WORDS];
    __shared__ float    bs[16];

    const int tid    = threadIdx.x;
    const int wid    = tid >> 5;
    const int lane   = tid & 31;
    const int q      = lane & 3;    // fragment k-quad
    const int lr     = lane >> 2;   // fragment row / n index (0..7)
    const int d      = blockIdx.y;
    const int bstart = blockIdx.x * PN;

    // Zero the x tile (halo + pad slots must be 0)
    {
        uint4* xz = reinterpret_cast<uint4*>(xs);
        const uint4 z = make_uint4(0u, 0u, 0u, 0u);
        for (int i = tid; i < XS_WORDS / 4; i += T1) xz[i] = z;
    }
    // Weights -> fp16 pairs, permuted. pre_w layout [tap][c][f].
    for (int i = tid; i < 1152; i += T1) {
        const int tap = i >> 7;
        const int rem = i & 127;
        const int f   = rem >> 3;
        const int j   = rem & 7;
        const int c   = (j & 1) ? (j + 7) : j;
        const int base = d * 2304 + tap * 256;
        const float wlo = pre_w[base + c * 16 + f];
        const float whi = pre_w[base + (c + 1) * 16 + f];
        wb[(tap * 16 + f) * 8 + j] = pack_f16x2(wlo, whi);
    }
    if (tid < FOUT) bs[tid] = pre_b[d * FOUT + tid];
    __syncthreads();

    // Gather: 272 (pt_h, w) rows; convert to permuted fp16, 2x STS.128
    for (int r = tid; r < 34 * 8; r += T1) {
        const int pt = r >> 3;
        const int w  = r & 7;
        const int gp = bstart - 1 + pt;
        if ((unsigned)gp >= NPTS) continue;
        const int idx = inv[(d * NPTS + gp) * BW + w];
        const float4* xp = reinterpret_cast<const float4*>(X) + idx * 4;
        const float4 v0 = xp[0], v1 = xp[1], v2 = xp[2], v3 = xp[3];
        uint4 o0, o1;
        o0.x = pack_f16x2(v0.x, v0.y);   // (c0,c1)
        o0.y = pack_f16x2(v2.x, v2.y);   // (c8,c9)
        o0.z = pack_f16x2(v0.z, v0.w);   // (c2,c3)
        o0.w = pack_f16x2(v2.z, v2.w);   // (c10,c11)
        o1.x = pack_f16x2(v1.x, v1.y);   // (c4,c5)
        o1.y = pack_f16x2(v3.x, v3.y);   // (c12,c13)
        o1.z = pack_f16x2(v1.z, v1.w);   // (c6,c7)
        o1.w = pack_f16x2(v3.z, v3.w);   // (c14,c15)
        uint4* dst = reinterpret_cast<uint4*>(xs + (pt * 10 + w + 1) * 8);
        dst[0] = o0; dst[1] = o1;
    }
    __syncthreads();

    // A-fragment bases: m-tile mt covers rows wid*32 + mt*16 + {lr, lr+8}
    // -> (pt = wid*4 + mt*2 (+1), w = lr); smem addr adds (a*10+b)*8 per tap.
    int base_lo[2], base_hi[2];
#pragma unroll
    for (int mt = 0; mt < 2; ++mt) {
        const int ptl = wid * 4 + mt * 2;
        base_lo[mt] = (ptl * 10 + lr) * 8 + 2 * q;
        base_hi[mt] = base_lo[mt] + 80;
    }

    float acc[2][2][4];
#pragma unroll
    for (int mt = 0; mt < 2; ++mt)
#pragma unroll
        for (int nt = 0; nt < 2; ++nt)
#pragma unroll
            for (int i = 0; i < 4; ++i) acc[mt][nt][i] = 0.f;

#pragma unroll
    for (int a = 0; a < 3; ++a) {
#pragma unroll
        for (int b = 0; b < 3; ++b) {
            const int tap  = a * 3 + b;
            const int toff = (a * 10 + b) * 8;
            // B fragments: one LDS.64 per n-tile
            const uint2 bf0 = *reinterpret_cast<const uint2*>(
                wb + (tap * 16 + lr) * 8 + 2 * q);
            const uint2 bf1 = *reinterpret_cast<const uint2*>(
                wb + (tap * 16 + 8 + lr) * 8 + 2 * q);
#pragma unroll
            for (int mt = 0; mt < 2; ++mt) {
                const uint2 alo = *reinterpret_cast<const uint2*>(
                    xs + base_lo[mt] + toff);          // a0 (k..), a2 (k+8..)
                const uint2 ahi = *reinterpret_cast<const uint2*>(
                    xs + base_hi[mt] + toff);          // a1, a3
                MMA_F16(acc[mt][0], alo.x, ahi.x, alo.y, ahi.y, bf0.x, bf0.y);
                MMA_F16(acc[mt][1], alo.x, ahi.x, alo.y, ahi.y, bf1.x, bf1.y);
            }
        }
    }

    // Epilogue: bias + relu + red.v2 into g_seg (all rows in-range: 100000%32==0)
#pragma unroll
    for (int mt = 0; mt < 2; ++mt) {
        const int ptl   = wid * 4 + mt * 2;
        const int seg_l = index[d * NPTS + bstart + ptl];
        const int seg_h = index[d * NPTS + bstart + ptl + 1];
        float* base_l = g_seg + ((d * NSEG + seg_l) * BW + lr) * FOUT;
        float* base_h = g_seg + ((d * NSEG + seg_h) * BW + lr) * FOUT;
#pragma unroll
        for (int nt = 0; nt < 2; ++nt) {
            const int col = nt * 8 + 2 * q;
            const float b0v = bs[col], b1v = bs[col + 1];
            const float v0 = fmaxf(acc[mt][nt][0] + b0v, 0.f);
            const float v1 = fmaxf(acc[mt][nt][1] + b1v, 0.f);
            const float v2 = fmaxf(acc[mt][nt][2] + b0v, 0.f);
            const float v3 = fmaxf(acc[mt][nt][3] + b1v, 0.f);
            asm volatile("red.global.add.v2.f32 [%0], {%1,%2};"
                         :: "l"(base_l + col), "f"(v0), "f"(v1) : "memory");
            asm volatile("red.global.add.v2.f32 [%0], {%1,%2};"
                         :: "l"(base_h + col), "f"(v2), "f"(v3) : "memory");
        }
    }
}

// ---------------------------------------------------------------------------
// Kernel 2: post conv (3,1) + relu on g_seg -> g_z
// ---------------------------------------------------------------------------
__global__ void __launch_bounds__(256)
post_conv_kernel(const float* __restrict__ post_w, const float* __restrict__ post_b)
{
    __shared__ float ws[768];
    __shared__ float bs[16];
    const int tid = threadIdx.x;
    const int d   = blockIdx.y;
    for (int i = tid; i < 768; i += 256) ws[i] = post_w[d * 768 + i];
    if (tid < FOUT) bs[tid] = post_b[d * FOUT + tid];
    __syncthreads();

    const int gt = blockIdx.x * 256 + tid;
    const int s  = gt >> 3;
    const int w  = gt & 7;

    float acc[16];
#pragma unroll
    for (int f = 0; f < 16; ++f) acc[f] = 0.f;

#pragma unroll
    for (int a = 0; a < 3; ++a) {
        const int ss = s + a - 1;
        if (ss < 0 || ss >= NSEG) continue;
        const float4* src = reinterpret_cast<const float4*>(
            g_seg + ((d * NSEG + ss) * BW + w) * FOUT);
#pragma unroll
        for (int cg = 0; cg < 4; ++cg) {
            const float4 x4 = src[cg];
            const float* wr = ws + (a * 16 + cg * 4) * 16;
#pragma unroll
            for (int f = 0; f < 16; ++f) acc[f] += x4.x * wr[f];
#pragma unroll
            for (int f = 0; f < 16; ++f) acc[f] += x4.y * wr[16 + f];
#pragma unroll
            for (int f = 0; f < 16; ++f) acc[f] += x4.z * wr[32 + f];
#pragma unroll
            for (int f = 0; f < 16; ++f) acc[f] += x4.w * wr[48 + f];
        }
    }

    float4* dst = reinterpret_cast<float4*>(g_z + ((d * NSEG + s) * BW + w) * FOUT);
#pragma unroll
    for (int fg = 0; fg < 4; ++fg) {
        float4 v;
        v.x = fmaxf(acc[fg * 4 + 0] + bs[fg * 4 + 0], 0.f);
        v.y = fmaxf(acc[fg * 4 + 1] + bs[fg * 4 + 1], 0.f);
        v.z = fmaxf(acc[fg * 4 + 2] + bs[fg * 4 + 2], 0.f);
        v.w = fmaxf(acc[fg * 4 + 3] + bs[fg * 4 + 3], 0.f);
        dst[fg] = v;
    }
}

// ---------------------------------------------------------------------------
// Kernel 3: Y[n,w,:] = sum_d g_z[d, index[d,n], w, :]
// ---------------------------------------------------------------------------
__global__ void __launch_bounds__(256)
gather_out_kernel(const int* __restrict__ index, float* __restrict__ out)
{
    const int gt = blockIdx.x * 256 + threadIdx.x;
    if (gt >= NPTS * BW * 4) return;
    const int n   = gt >> 5;
    const int rem = gt & 31;

    const int s0 = index[n];
    const int s1 = index[NPTS + n];
    const int s2 = index[2 * NPTS + n];

    const float4* b0 = reinterpret_cast<const float4*>(
        g_z + (size_t)s0 * (BW * FOUT)) + rem;
    const float4* b1 = reinterpret_cast<const float4*>(
        g_z + (size_t)(NSEG + s1) * (BW * FOUT)) + rem;
    const float4* b2 = reinterpret_cast<const float4*>(
        g_z + (size_t)(2 * NSEG + s2) * (BW * FOUT)) + rem;

    const float4 v0 = *b0;
    const float4 v1 = *b1;
    const float4 v2 = *b2;

    float4 r;
    r.x = v0.x + v1.x + v2.x;
    r.y = v0.y + v1.y + v2.y;
    r.z = v0.z + v1.z + v2.z;
    r.w = v0.w + v1.w + v2.w;
    reinterpret_cast<float4*>(out)[gt] = r;
}

// ---------------------------------------------------------------------------
extern "C" void kernel_launch(void* const* d_in, const int* in_sizes, int n_in,
                              void* d_out, int out_size)
{
    const float* X      = (const float*)d_in[0];
    const int*   inv    = (const int*)  d_in[1];
    const int*   index  = (const int*)  d_in[2];
    const float* pre_w  = (const float*)d_in[3];
    const float* pre_b  = (const float*)d_in[4];
    const float* post_w = (const float*)d_in[5];
    const float* post_b = (const float*)d_in[6];
    float*       out    = (float*)      d_out;

    zero_seg_kernel<<<2048, 256>>>();

    dim3 g1(NB, NDIM);
    pre_conv_mma_kernel<<<g1, T1>>>(X, inv, index, pre_w, pre_b);

    dim3 g2(NSEG * BW / 256, NDIM);
    post_conv_kernel<<<g2, 256>>>(post_w, post_b);

    gather_out_kernel<<<(NPTS * BW * 4 + 255) / 256, 256>>>(index, out);
}

// round 9
// speedup vs baseline: 2.5959x; 1.0142x over previous
#include <cuda_runtime.h>
#include <cstdint>

// Problem constants
#define NPTS 100000
#define CIN  16
#define FOUT 16
#define BW   8
#define NDIM 3
#define NSEG 8192

// Pre-conv (fp16 mma.sync m16n8k16) tiling
#define PN    32                  // points per CTA -> 256 output rows
#define T1    256                 // 8 warps; warp covers 32 rows (2 m16 tiles)
#define NB    (NPTS / PN)         // 3125
#define XS_WORDS (34 * 10 * 8)    // 2720: (PN+2 pt-halo) x 10 w-slots x 8 words
#define WB_WORDS (144 * 8)        // 1152: 9 taps x 16 filter rows x 8 words

__device__ __forceinline__ uint32_t pack_f16x2(float lo, float hi) {
    uint32_t r;
    asm("cvt.rn.f16x2.f32 %0, %1, %2;" : "=r"(r) : "f"(hi), "f"(lo));
    return r;
}

#define MMA_F16(acc, a0, a1, a2, a3, b0, b1)                                   \
    asm("mma.sync.aligned.m16n8k16.row.col.f32.f16.f16.f32 "                   \
        "{%0,%1,%2,%3},{%4,%5,%6,%7},{%8,%9},{%0,%1,%2,%3};"                   \
        : "+f"(acc[0]), "+f"(acc[1]), "+f"(acc[2]), "+f"(acc[3])               \
        : "r"(a0), "r"(a1), "r"(a2), "r"(a3), "r"(b0), "r"(b1))

// Device scratch (static allocation — no cudaMalloc allowed)
__device__ float g_seg[NDIM * NSEG * BW * FOUT];   // segment sums, 12.6 MB
__device__ float g_z  [NDIM * NSEG * BW * FOUT];   // post-conv output, 12.6 MB

// ---------------------------------------------------------------------------
// Kernel 0: zero the segment-sum scratch
// ---------------------------------------------------------------------------
__global__ void zero_seg_kernel() {
    const int total = NDIM * NSEG * BW * FOUT / 4;
    float4* p = reinterpret_cast<float4*>(g_seg);
    const float4 z = make_float4(0.f, 0.f, 0.f, 0.f);
    for (int i = blockIdx.x * blockDim.x + threadIdx.x; i < total;
         i += gridDim.x * blockDim.x)
        p[i] = z;
}

// ---------------------------------------------------------------------------
// Kernel 1: gather X[inv] -> fp16 mma 3x3 conv -> relu -> atomic seg-sum
// grid (3125, 3), block 256 (8 warps). Warp wid: output rows [32wid, 32wid+32).
// smem x tile: row = pt_h*10 + wslot, 8 words/row (32B fp16), channel words
// pair-permuted: word j = (c_j, c_{j+1}) for even j, (c_{j+7}, c_{j+8}) odd j.
// B tiles FILTER-permuted so each thread's D cols are filters [4q, 4q+4):
//   tile nt, B-row n  holds filter 4*(n>>1) + 2*nt + (n&1)
// -> epilogue is ONE red.v4 per (m-tile, row-half): 4 red.v4/thread.
// GEMM: M=256 rows, N=16 filters, K=144 as 9 taps x k16 (implicit im2col).
// ---------------------------------------------------------------------------
__global__ void __launch_bounds__(T1)
pre_conv_mma_kernel(const float* __restrict__ X, const int* __restrict__ inv,
                    const int* __restrict__ index,
                    const float* __restrict__ pre_w, const float* __restrict__ pre_b)
{
    __shared__ uint32_t xs[XS_WORDS];
    __shared__ uint32_t wb[WB_WORDS];
    __shared__ float    bs[16];        // bias in ORIGINAL filter order

    const int tid    = threadIdx.x;
    const int wid    = tid >> 5;
    const int lane   = tid & 31;
    const int q      = lane & 3;    // fragment k-quad / D col group
    const int lr     = lane >> 2;   // fragment row / B n index (0..7)
    const int d      = blockIdx.y;
    const int bstart = blockIdx.x * PN;

    // Zero the x tile (halo + pad slots must be 0)
    {
        uint4* xz = reinterpret_cast<uint4*>(xs);
        const uint4 z = make_uint4(0u, 0u, 0u, 0u);
        for (int i = tid; i < XS_WORDS / 4; i += T1) xz[i] = z;
    }
    // Weights -> fp16 pairs, channel-permuted words, filter-permuted rows.
    // pre_w layout [tap][c][f]. Storage row s = nt*8+n -> filter fperm.
    for (int i = tid; i < 1152; i += T1) {
        const int tap = i >> 7;
        const int rem = i & 127;
        const int s   = rem >> 3;                    // storage row 0..15
        const int j   = rem & 7;
        const int nt  = s >> 3;
        const int n   = s & 7;
        const int fpm = 4 * (n >> 1) + 2 * nt + (n & 1);
        const int c   = (j & 1) ? (j + 7) : j;
        const int base = d * 2304 + tap * 256;
        const float wlo = pre_w[base + c * 16 + fpm];
        const float whi = pre_w[base + (c + 1) * 16 + fpm];
        wb[(tap * 16 + s) * 8 + j] = pack_f16x2(wlo, whi);
    }
    if (tid < FOUT) bs[tid] = pre_b[d * FOUT + tid];
    __syncthreads();

    // Gather: 272 (pt_h, w) rows; convert to permuted fp16, 2x STS.128
    for (int r = tid; r < 34 * 8; r += T1) {
        const int pt = r >> 3;
        const int w  = r & 7;
        const int gp = bstart - 1 + pt;
        if ((unsigned)gp >= NPTS) continue;
        const int idx = inv[(d * NPTS + gp) * BW + w];
        const float4* xp = reinterpret_cast<const float4*>(X) + idx * 4;
        const float4 v0 = xp[0], v1 = xp[1], v2 = xp[2], v3 = xp[3];
        uint4 o0, o1;
        o0.x = pack_f16x2(v0.x, v0.y);   // (c0,c1)
        o0.y = pack_f16x2(v2.x, v2.y);   // (c8,c9)
        o0.z = pack_f16x2(v0.z, v0.w);   // (c2,c3)
        o0.w = pack_f16x2(v2.z, v2.w);   // (c10,c11)
        o1.x = pack_f16x2(v1.x, v1.y);   // (c4,c5)
        o1.y = pack_f16x2(v3.x, v3.y);   // (c12,c13)
        o1.z = pack_f16x2(v1.z, v1.w);   // (c6,c7)
        o1.w = pack_f16x2(v3.z, v3.w);   // (c14,c15)
        uint4* dst = reinterpret_cast<uint4*>(xs + (pt * 10 + w + 1) * 8);
        dst[0] = o0; dst[1] = o1;
    }
    __syncthreads();

    // A-fragment bases: m-tile mt covers rows wid*32 + mt*16 + {lr, lr+8}
    // -> (pt = wid*4 + mt*2 (+1), w = lr); smem addr adds (a*10+b)*8 per tap.
    int base_lo[2], base_hi[2];
#pragma unroll
    for (int mt = 0; mt < 2; ++mt) {
        const int ptl = wid * 4 + mt * 2;
        base_lo[mt] = (ptl * 10 + lr) * 8 + 2 * q;
        base_hi[mt] = base_lo[mt] + 80;
    }

    float acc[2][2][4];
#pragma unroll
    for (int mt = 0; mt < 2; ++mt)
#pragma unroll
        for (int nt = 0; nt < 2; ++nt)
#pragma unroll
            for (int i = 0; i < 4; ++i) acc[mt][nt][i] = 0.f;

#pragma unroll
    for (int a = 0; a < 3; ++a) {
#pragma unroll
        for (int b = 0; b < 3; ++b) {
            const int tap  = a * 3 + b;
            const int toff = (a * 10 + b) * 8;
            // B fragments: one LDS.64 per n-tile
            const uint2 bf0 = *reinterpret_cast<const uint2*>(
                wb + (tap * 16 + lr) * 8 + 2 * q);
            const uint2 bf1 = *reinterpret_cast<const uint2*>(
                wb + (tap * 16 + 8 + lr) * 8 + 2 * q);
#pragma unroll
            for (int mt = 0; mt < 2; ++mt) {
                const uint2 alo = *reinterpret_cast<const uint2*>(
                    xs + base_lo[mt] + toff);          // a0 (k..), a2 (k+8..)
                const uint2 ahi = *reinterpret_cast<const uint2*>(
                    xs + base_hi[mt] + toff);          // a1, a3
                MMA_F16(acc[mt][0], alo.x, ahi.x, alo.y, ahi.y, bf0.x, bf0.y);
                MMA_F16(acc[mt][1], alo.x, ahi.x, alo.y, ahi.y, bf1.x, bf1.y);
            }
        }
    }

    // Epilogue: bias + relu + ONE red.v4 per (mt, half). Thread's cols are
    // filters 4q..4q+3: {nt0.e0, nt0.e1, nt1.e0, nt1.e1} = {4q,4q+1,4q+2,4q+3}.
    const float bq0 = bs[4 * q + 0], bq1 = bs[4 * q + 1];
    const float bq2 = bs[4 * q + 2], bq3 = bs[4 * q + 3];
#pragma unroll
    for (int mt = 0; mt < 2; ++mt) {
        const int ptl   = wid * 4 + mt * 2;
        const int seg_l = index[d * NPTS + bstart + ptl];
        const int seg_h = index[d * NPTS + bstart + ptl + 1];
        float* base_l = g_seg + ((d * NSEG + seg_l) * BW + lr) * FOUT + 4 * q;
        float* base_h = g_seg + ((d * NSEG + seg_h) * BW + lr) * FOUT + 4 * q;
        {
            const float v0 = fmaxf(acc[mt][0][0] + bq0, 0.f);
            const float v1 = fmaxf(acc[mt][0][1] + bq1, 0.f);
            const float v2 = fmaxf(acc[mt][1][0] + bq2, 0.f);
            const float v3 = fmaxf(acc[mt][1][1] + bq3, 0.f);
            asm volatile("red.global.add.v4.f32 [%0], {%1,%2,%3,%4};"
                         :: "l"(base_l), "f"(v0), "f"(v1), "f"(v2), "f"(v3)
                         : "memory");
        }
        {
            const float v0 = fmaxf(acc[mt][0][2] + bq0, 0.f);
            const float v1 = fmaxf(acc[mt][0][3] + bq1, 0.f);
            const float v2 = fmaxf(acc[mt][1][2] + bq2, 0.f);
            const float v3 = fmaxf(acc[mt][1][3] + bq3, 0.f);
            asm volatile("red.global.add.v4.f32 [%0], {%1,%2,%3,%4};"
                         :: "l"(base_h), "f"(v0), "f"(v1), "f"(v2), "f"(v3)
                         : "memory");
        }
    }
}

// ---------------------------------------------------------------------------
// Kernel 2: post conv (3,1) + relu on g_seg -> g_z
// ---------------------------------------------------------------------------
__global__ void __launch_bounds__(256)
post_conv_kernel(const float* __restrict__ post_w, const float* __restrict__ post_b)
{
    __shared__ float ws[768];
    __shared__ float bs[16];
    const int tid = threadIdx.x;
    const int d   = blockIdx.y;
    for (int i = tid; i < 768; i += 256) ws[i] = post_w[d * 768 + i];
    if (tid < FOUT) bs[tid] = post_b[d * FOUT + tid];
    __syncthreads();

    const int gt = blockIdx.x * 256 + tid;
    const int s  = gt >> 3;
    const int w  = gt & 7;

    float acc[16];
#pragma unroll
    for (int f = 0; f < 16; ++f) acc[f] = 0.f;

#pragma unroll
    for (int a = 0; a < 3; ++a) {
        const int ss = s + a - 1;
        if (ss < 0 || ss >= NSEG) continue;
        const float4* src = reinterpret_cast<const float4*>(
            g_seg + ((d * NSEG + ss) * BW + w) * FOUT);
#pragma unroll
        for (int cg = 0; cg < 4; ++cg) {
            const float4 x4 = src[cg];
            const float* wr = ws + (a * 16 + cg * 4) * 16;
#pragma unroll
            for (int f = 0; f < 16; ++f) acc[f] += x4.x * wr[f];
#pragma unroll
            for (int f = 0; f < 16; ++f) acc[f] += x4.y * wr[16 + f];
#pragma unroll
            for (int f = 0; f < 16; ++f) acc[f] += x4.z * wr[32 + f];
#pragma unroll
            for (int f = 0; f < 16; ++f) acc[f] += x4.w * wr[48 + f];
        }
    }

    float4* dst = reinterpret_cast<float4*>(g_z + ((d * NSEG + s) * BW + w) * FOUT);
#pragma unroll
    for (int fg = 0; fg < 4; ++fg) {
        float4 v;
        v.x = fmaxf(acc[fg * 4 + 0] + bs[fg * 4 + 0], 0.f);
        v.y = fmaxf(acc[fg * 4 + 1] + bs[fg * 4 + 1], 0.f);
        v.z = fmaxf(acc[fg * 4 + 2] + bs[fg * 4 + 2], 0.f);
        v.w = fmaxf(acc[fg * 4 + 3] + bs[fg * 4 + 3], 0.f);
        dst[fg] = v;
    }
}

// ---------------------------------------------------------------------------
// Kernel 3: Y[n,w,:] = sum_d g_z[d, index[d,n], w, :]
// ---------------------------------------------------------------------------
__global__ void __launch_bounds__(256)
gather_out_kernel(const int* __restrict__ index, float* __restrict__ out)
{
    const int gt = blockIdx.x * 256 + threadIdx.x;
    if (gt >= NPTS * BW * 4) return;
    const int n   = gt >> 5;
    const int rem = gt & 31;

    const int s0 = index[n];
    const int s1 = index[NPTS + n];
    const int s2 = index[2 * NPTS + n];

    const float4* b0 = reinterpret_cast<const float4*>(
        g_z + (size_t)s0 * (BW * FOUT)) + rem;
    const float4* b1 = reinterpret_cast<const float4*>(
        g_z + (size_t)(NSEG + s1) * (BW * FOUT)) + rem;
    const float4* b2 = reinterpret_cast<const float4*>(
        g_z + (size_t)(2 * NSEG + s2) * (BW * FOUT)) + rem;

    const float4 v0 = *b0;
    const float4 v1 = *b1;
    const float4 v2 = *b2;

    float4 r;
    r.x = v0.x + v1.x + v2.x;
    r.y = v0.y + v1.y + v2.y;
    r.z = v0.z + v1.z + v2.z;
    r.w = v0.w + v1.w + v2.w;
    reinterpret_cast<float4*>(out)[gt] = r;
}

// ---------------------------------------------------------------------------
extern "C" void kernel_launch(void* const* d_in, const int* in_sizes, int n_in,
                              void* d_out, int out_size)
{
    const float* X      = (const float*)d_in[0];
    const int*   inv    = (const int*)  d_in[1];
    const int*   index  = (const int*)  d_in[2];
    const float* pre_w  = (const float*)d_in[3];
    const float* pre_b  = (const float*)d_in[4];
    const float* post_w = (const float*)d_in[5];
    const float* post_b = (const float*)d_in[6];
    float*       out    = (float*)      d_out;

    zero_seg_kernel<<<2048, 256>>>();

    dim3 g1(NB, NDIM);
    pre_conv_mma_kernel<<<g1, T1>>>(X, inv, index, pre_w, pre_b);

    dim3 g2(NSEG * BW / 256, NDIM);
    post_conv_kernel<<<g2, 256>>>(post_w, post_b);

    gather_out_kernel<<<(NPTS * BW * 4 + 255) / 256, 256>>>(index, out);
}

// round 10
// speedup vs baseline: 2.6805x; 1.0326x over previous
#include <cuda_runtime.h>
#include <cstdint>

// Problem constants
#define NPTS 100000
#define CIN  16
#define FOUT 16
#define BW   8
#define NDIM 3
#define NSEG 8192

// Pre-conv (fp16 mma.sync m16n8k16) tiling
#define PN    32                  // points per CTA -> 256 output rows
#define T1    256                 // 8 warps; warp covers 32 rows (2 m16 tiles)
#define NB    (NPTS / PN)         // 3125
#define XS_WORDS (34 * 10 * 8)    // 2720: (PN+2 pt-halo) x 10 w-slots x 8 words
#define WB_WORDS (144 * 8)        // 1152: 9 taps x 16 filter rows x 8 words

__device__ __forceinline__ uint32_t pack_f16x2(float lo, float hi) {
    uint32_t r;
    asm("cvt.rn.f16x2.f32 %0, %1, %2;" : "=r"(r) : "f"(hi), "f"(lo));
    return r;
}

#define MMA_F16(acc, a0, a1, a2, a3, b0, b1)                                   \
    asm("mma.sync.aligned.m16n8k16.row.col.f32.f16.f16.f32 "                   \
        "{%0,%1,%2,%3},{%4,%5,%6,%7},{%8,%9},{%0,%1,%2,%3};"                   \
        : "+f"(acc[0]), "+f"(acc[1]), "+f"(acc[2]), "+f"(acc[3])               \
        : "r"(a0), "r"(a1), "r"(a2), "r"(a3), "r"(b0), "r"(b1))

// Device scratch (static allocation — no cudaMalloc allowed)
__device__ float g_seg[NDIM * NSEG * BW * FOUT];   // segment sums, 12.6 MB
__device__ float g_z  [NDIM * NSEG * BW * FOUT];   // post-conv output, 12.6 MB

// ---------------------------------------------------------------------------
// Kernel 0: zero the segment-sum scratch
// ---------------------------------------------------------------------------
__global__ void zero_seg_kernel() {
    const int total = NDIM * NSEG * BW * FOUT / 4;
    float4* p = reinterpret_cast<float4*>(g_seg);
    const float4 z = make_float4(0.f, 0.f, 0.f, 0.f);
    for (int i = blockIdx.x * blockDim.x + threadIdx.x; i < total;
         i += gridDim.x * blockDim.x)
        p[i] = z;
}

// ---------------------------------------------------------------------------
// Kernel 1: gather X[inv] -> fp16 mma 3x3 conv -> relu -> atomic seg-sum
// grid (3125, 3), block 256 (8 warps). Warp wid: output rows [32wid, 32wid+32).
// smem x tile: row = pt_h*10 + wslot, 8 words/row (32B fp16), channel words
// pair-permuted: w0=(c0,c1) w1=(c8,c9) w2=(c2,c3) w3=(c10,c11)
//                w4=(c4,c5) w5=(c12,c13) w6=(c6,c7) w7=(c14,c15)
// Gather is QUAD-COOPERATIVE: 4 lanes split one row's 64B (16B each) so the
// whole row coalesces to ONE L1tex line access per instruction (4x fewer
// wavefronts). Lane t covers channels 4t..4t+3 -> words {woff, woff+2},
// woff = 4*(t&1) + (t>>1).
// B tiles FILTER-permuted so each thread's D cols are filters [4q, 4q+4):
//   tile nt, B-row n holds filter 4*(n>>1) + 2*nt + (n&1)
// -> epilogue is ONE red.v4 per (m-tile, row-half).
// GEMM: M=256 rows, N=16 filters, K=144 as 9 taps x k16 (implicit im2col).
// ---------------------------------------------------------------------------
__global__ void __launch_bounds__(T1)
pre_conv_mma_kernel(const float* __restrict__ X, const int* __restrict__ inv,
                    const int* __restrict__ index,
                    const float* __restrict__ pre_w, const float* __restrict__ pre_b)
{
    __shared__ uint32_t xs[XS_WORDS];
    __shared__ uint32_t wb[WB_WORDS];
    __shared__ float    bs[16];        // bias in ORIGINAL filter order

    const int tid    = threadIdx.x;
    const int wid    = tid >> 5;
    const int lane   = tid & 31;
    const int q      = lane & 3;    // fragment k-quad / D col group
    const int lr     = lane >> 2;   // fragment row / B n index (0..7)
    const int d      = blockIdx.y;
    const int bstart = blockIdx.x * PN;

    // Zero only rows the gather may not write:
    //  - w-pad slots (wslot 0 and 9) for all 34 pt rows: 68 rows
    //  - pt halo rows 0 and 33, wslots 1..8 (unwritten only at grid edges): 16 rows
    for (int i = tid; i < 34 * 16; i += T1) {       // pad slots
        const int pt = i >> 4, rem = i & 15;
        const int wslot = (rem < 8) ? 0 : 9;
        xs[(pt * 10 + wslot) * 8 + (rem & 7)] = 0u;
    }
    for (int i = tid; i < 2 * 8 * 8; i += T1) {     // halo pt rows
        const int pt = (i >> 6) ? 33 : 0;
        const int wslot = ((i >> 3) & 7) + 1;
        xs[(pt * 10 + wslot) * 8 + (i & 7)] = 0u;
    }

    // Weights -> fp16 pairs, channel-permuted words, filter-permuted rows.
    // pre_w layout [tap][c][f]. Storage row s = nt*8+n -> filter fperm.
    for (int i = tid; i < 1152; i += T1) {
        const int tap = i >> 7;
        const int rem = i & 127;
        const int s   = rem >> 3;                    // storage row 0..15
        const int j   = rem & 7;
        const int nt  = s >> 3;
        const int n   = s & 7;
        const int fpm = 4 * (n >> 1) + 2 * nt + (n & 1);
        const int c   = (j & 1) ? (j + 7) : j;
        const int base = d * 2304 + tap * 256;
        const float wlo = pre_w[base + c * 16 + fpm];
        const float whi = pre_w[base + (c + 1) * 16 + fpm];
        wb[(tap * 16 + s) * 8 + j] = pack_f16x2(wlo, whi);
    }
    if (tid < FOUT) bs[tid] = pre_b[d * FOUT + tid];
    __syncthreads();

    // Quad-cooperative gather: 272 rows x 4 quarters = 1088 lane tasks
    for (int i = tid; i < 34 * 8 * 4; i += T1) {
        const int r  = i >> 2;          // row 0..271
        const int t  = i & 3;           // 16B quarter
        const int pt = r >> 3;
        const int w  = r & 7;
        const int gp = bstart - 1 + pt;
        if ((unsigned)gp >= NPTS) continue;
        const int idx = inv[(d * NPTS + gp) * BW + w];   // quad-uniform, coalesced
        const float4 v = reinterpret_cast<const float4*>(X)[idx * 4 + t];
        const int woff = (pt * 10 + w + 1) * 8 + 4 * (t & 1) + (t >> 1);
        xs[woff]     = pack_f16x2(v.x, v.y);   // (c4t,   c4t+1)
        xs[woff + 2] = pack_f16x2(v.z, v.w);   // (c4t+2, c4t+3)
    }
    __syncthreads();

    // A-fragment bases: m-tile mt covers rows wid*32 + mt*16 + {lr, lr+8}
    // -> (pt = wid*4 + mt*2 (+1), w = lr); smem addr adds (a*10+b)*8 per tap.
    int base_lo[2], base_hi[2];
#pragma unroll
    for (int mt = 0; mt < 2; ++mt) {
        const int ptl = wid * 4 + mt * 2;
        base_lo[mt] = (ptl * 10 + lr) * 8 + 2 * q;
        base_hi[mt] = base_lo[mt] + 80;
    }

    float acc[2][2][4];
#pragma unroll
    for (int mt = 0; mt < 2; ++mt)
#pragma unroll
        for (int nt = 0; nt < 2; ++nt)
#pragma unroll
            for (int i = 0; i < 4; ++i) acc[mt][nt][i] = 0.f;

#pragma unroll
    for (int a = 0; a < 3; ++a) {
#pragma unroll
        for (int b = 0; b < 3; ++b) {
            const int tap  = a * 3 + b;
            const int toff = (a * 10 + b) * 8;
            // B fragments: one LDS.64 per n-tile
            const uint2 bf0 = *reinterpret_cast<const uint2*>(
                wb + (tap * 16 + lr) * 8 + 2 * q);
            const uint2 bf1 = *reinterpret_cast<const uint2*>(
                wb + (tap * 16 + 8 + lr) * 8 + 2 * q);
#pragma unroll
            for (int mt = 0; mt < 2; ++mt) {
                const uint2 alo = *reinterpret_cast<const uint2*>(
                    xs + base_lo[mt] + toff);          // a0 (k..), a2 (k+8..)
                const uint2 ahi = *reinterpret_cast<const uint2*>(
                    xs + base_hi[mt] + toff);          // a1, a3
                MMA_F16(acc[mt][0], alo.x, ahi.x, alo.y, ahi.y, bf0.x, bf0.y);
                MMA_F16(acc[mt][1], alo.x, ahi.x, alo.y, ahi.y, bf1.x, bf1.y);
            }
        }
    }

    // Epilogue: bias + relu + ONE red.v4 per (mt, half). Thread's cols are
    // filters 4q..4q+3: {nt0.e0, nt0.e1, nt1.e0, nt1.e1} = {4q,4q+1,4q+2,4q+3}.
    const float bq0 = bs[4 * q + 0], bq1 = bs[4 * q + 1];
    const float bq2 = bs[4 * q + 2], bq3 = bs[4 * q + 3];
#pragma unroll
    for (int mt = 0; mt < 2; ++mt) {
        const int ptl   = wid * 4 + mt * 2;
        const int seg_l = index[d * NPTS + bstart + ptl];
        const int seg_h = index[d * NPTS + bstart + ptl + 1];
        float* base_l = g_seg + ((d * NSEG + seg_l) * BW + lr) * FOUT + 4 * q;
        float* base_h = g_seg + ((d * NSEG + seg_h) * BW + lr) * FOUT + 4 * q;
        {
            const float v0 = fmaxf(acc[mt][0][0] + bq0, 0.f);
            const float v1 = fmaxf(acc[mt][0][1] + bq1, 0.f);
            const float v2 = fmaxf(acc[mt][1][0] + bq2, 0.f);
            const float v3 = fmaxf(acc[mt][1][1] + bq3, 0.f);
            asm volatile("red.global.add.v4.f32 [%0], {%1,%2,%3,%4};"
                         :: "l"(base_l), "f"(v0), "f"(v1), "f"(v2), "f"(v3)
                         : "memory");
        }
        {
            const float v0 = fmaxf(acc[mt][0][2] + bq0, 0.f);
            const float v1 = fmaxf(acc[mt][0][3] + bq1, 0.f);
            const float v2 = fmaxf(acc[mt][1][2] + bq2, 0.f);
            const float v3 = fmaxf(acc[mt][1][3] + bq3, 0.f);
            asm volatile("red.global.add.v4.f32 [%0], {%1,%2,%3,%4};"
                         :: "l"(base_h), "f"(v0), "f"(v1), "f"(v2), "f"(v3)
                         : "memory");
        }
    }
}

// ---------------------------------------------------------------------------
// Kernel 2: post conv (3,1) + relu on g_seg -> g_z
// ---------------------------------------------------------------------------
__global__ void __launch_bounds__(256)
post_conv_kernel(const float* __restrict__ post_w, const float* __restrict__ post_b)
{
    __shared__ float ws[768];
    __shared__ float bs[16];
    const int tid = threadIdx.x;
    const int d   = blockIdx.y;
    for (int i = tid; i < 768; i += 256) ws[i] = post_w[d * 768 + i];
    if (tid < FOUT) bs[tid] = post_b[d * FOUT + tid];
    __syncthreads();

    const int gt = blockIdx.x * 256 + tid;
    const int s  = gt >> 3;
    const int w  = gt & 7;

    float acc[16];
#pragma unroll
    for (int f = 0; f < 16; ++f) acc[f] = 0.f;

#pragma unroll
    for (int a = 0; a < 3; ++a) {
        const int ss = s + a - 1;
        if (ss < 0 || ss >= NSEG) continue;
        const float4* src = reinterpret_cast<const float4*>(
            g_seg + ((d * NSEG + ss) * BW + w) * FOUT);
#pragma unroll
        for (int cg = 0; cg < 4; ++cg) {
            const float4 x4 = src[cg];
            const float* wr = ws + (a * 16 + cg * 4) * 16;
#pragma unroll
            for (int f = 0; f < 16; ++f) acc[f] += x4.x * wr[f];
#pragma unroll
            for (int f = 0; f < 16; ++f) acc[f] += x4.y * wr[16 + f];
#pragma unroll
            for (int f = 0; f < 16; ++f) acc[f] += x4.z * wr[32 + f];
#pragma unroll
            for (int f = 0; f < 16; ++f) acc[f] += x4.w * wr[48 + f];
        }
    }

    float4* dst = reinterpret_cast<float4*>(g_z + ((d * NSEG + s) * BW + w) * FOUT);
#pragma unroll
    for (int fg = 0; fg < 4; ++fg) {
        float4 v;
        v.x = fmaxf(acc[fg * 4 + 0] + bs[fg * 4 + 0], 0.f);
        v.y = fmaxf(acc[fg * 4 + 1] + bs[fg * 4 + 1], 0.f);
        v.z = fmaxf(acc[fg * 4 + 2] + bs[fg * 4 + 2], 0.f);
        v.w = fmaxf(acc[fg * 4 + 3] + bs[fg * 4 + 3], 0.f);
        dst[fg] = v;
    }
}

// ---------------------------------------------------------------------------
// Kernel 3: Y[n,w,:] = sum_d g_z[d, index[d,n], w, :]
// ---------------------------------------------------------------------------
__global__ void __launch_bounds__(256)
gather_out_kernel(const int* __restrict__ index, float* __restrict__ out)
{
    const int gt = blockIdx.x * 256 + threadIdx.x;
    if (gt >= NPTS * BW * 4) return;
    const int n   = gt >> 5;
    const int rem = gt & 31;

    const int s0 = index[n];
    const int s1 = index[NPTS + n];
    const int s2 = index[2 * NPTS + n];

    const float4* b0 = reinterpret_cast<const float4*>(
        g_z + (size_t)s0 * (BW * FOUT)) + rem;
    const float4* b1 = reinterpret_cast<const float4*>(
        g_z + (size_t)(NSEG + s1) * (BW * FOUT)) + rem;
    const float4* b2 = reinterpret_cast<const float4*>(
        g_z + (size_t)(2 * NSEG + s2) * (BW * FOUT)) + rem;

    const float4 v0 = *b0;
    const float4 v1 = *b1;
    const float4 v2 = *b2;

    float4 r;
    r.x = v0.x + v1.x + v2.x;
    r.y = v0.y + v1.y + v2.y;
    r.z = v0.z + v1.z + v2.z;
    r.w = v0.w + v1.w + v2.w;
    reinterpret_cast<float4*>(out)[gt] = r;
}

// ---------------------------------------------------------------------------
extern "C" void kernel_launch(void* const* d_in, const int* in_sizes, int n_in,
                              void* d_out, int out_size)
{
    const float* X      = (const float*)d_in[0];
    const int*   inv    = (const int*)  d_in[1];
    const int*   index  = (const int*)  d_in[2];
    const float* pre_w  = (const float*)d_in[3];
    const float* pre_b  = (const float*)d_in[4];
    const float* post_w = (const float*)d_in[5];
    const float* post_b = (const float*)d_in[6];
    float*       out    = (float*)      d_out;

    zero_seg_kernel<<<2048, 256>>>();

    dim3 g1(NB, NDIM);
    pre_conv_mma_kernel<<<g1, T1>>>(X, inv, index, pre_w, pre_b);

    dim3 g2(NSEG * BW / 256, NDIM);
    post_conv_kernel<<<g2, 256>>>(post_w, post_b);

    gather_out_kernel<<<(NPTS * BW * 4 + 255) / 256, 256>>>(index, out);
}

// round 11
// speedup vs baseline: 2.7481x; 1.0252x over previous
#include <cuda_runtime.h>
#include <cstdint>

// Problem constants
#define NPTS 100000
#define CIN  16
#define FOUT 16
#define BW   8
#define NDIM 3
#define NSEG 8192

// Pre-conv (fp16 mma.sync m16n8k16) tiling — persistent over tiles
#define PN    32                  // points per tile -> 256 output rows
#define T1    256                 // 8 warps; warp covers 32 rows (2 m16 tiles)
#define NTILE (NPTS / PN)         // 3125
#define TPC   5                   // tiles per CTA
#define NBX   (NTILE / TPC)       // 625
#define XS_WORDS (34 * 10 * 8)    // 2720
#define WB_WORDS (144 * 8)        // 1152

__device__ __forceinline__ uint32_t pack_f16x2(float lo, float hi) {
    uint32_t r;
    asm("cvt.rn.f16x2.f32 %0, %1, %2;" : "=r"(r) : "f"(hi), "f"(lo));
    return r;
}

#define MMA_F16(acc, a0, a1, a2, a3, b0, b1)                                   \
    asm("mma.sync.aligned.m16n8k16.row.col.f32.f16.f16.f32 "                   \
        "{%0,%1,%2,%3},{%4,%5,%6,%7},{%8,%9},{%0,%1,%2,%3};"                   \
        : "+f"(acc[0]), "+f"(acc[1]), "+f"(acc[2]), "+f"(acc[3])               \
        : "r"(a0), "r"(a1), "r"(a2), "r"(a3), "r"(b0), "r"(b1))

// Device scratch (static allocation — no cudaMalloc allowed)
__device__ float    g_seg[NDIM * NSEG * BW * FOUT];   // segment sums
__device__ float    g_z  [NDIM * NSEG * BW * FOUT];   // post-conv output
__device__ uint32_t g_wb [NDIM * WB_WORDS];           // permuted fp16 weights
__device__ float    g_bs [NDIM * FOUT];               // bias

// ---------------------------------------------------------------------------
// Kernel 0: zero the segment-sum scratch
// ---------------------------------------------------------------------------
__global__ void zero_seg_kernel() {
    const int total = NDIM * NSEG * BW * FOUT / 4;
    float4* p = reinterpret_cast<float4*>(g_seg);
    const float4 z = make_float4(0.f, 0.f, 0.f, 0.f);
    for (int i = blockIdx.x * blockDim.x + threadIdx.x; i < total;
         i += gridDim.x * blockDim.x)
        p[i] = z;
}

// ---------------------------------------------------------------------------
// Kernel 0b: permute + convert weights to fp16 ONCE (was per-CTA: ~720
// scattered L1tex wavefronts per CTA). pre_w layout [d][tap][c][f].
// Storage row s = nt*8+n holds filter fpm = 4*(n>>1)+2*nt+(n&1); word j holds
// channel pair (c, c+1) with c = j odd ? j+7 : j.
// ---------------------------------------------------------------------------
__global__ void weight_setup_kernel(const float* __restrict__ pre_w,
                                    const float* __restrict__ pre_b) {
    for (int gi = blockIdx.x * blockDim.x + threadIdx.x; gi < NDIM * WB_WORDS;
         gi += gridDim.x * blockDim.x) {
        const int d   = gi / WB_WORDS;
        const int i   = gi - d * WB_WORDS;
        const int tap = i >> 7;
        const int rem = i & 127;
        const int s   = rem >> 3;
        const int j   = rem & 7;
        const int nt  = s >> 3;
        const int n   = s & 7;
        const int fpm = 4 * (n >> 1) + 2 * nt + (n & 1);
        const int c   = (j & 1) ? (j + 7) : j;
        const int base = d * 2304 + tap * 256;
        g_wb[gi] = pack_f16x2(pre_w[base + c * 16 + fpm],
                              pre_w[base + (c + 1) * 16 + fpm]);
    }
    const int t = blockIdx.x * blockDim.x + threadIdx.x;
    if (t < NDIM * FOUT) g_bs[t] = pre_b[t];
}

// ---------------------------------------------------------------------------
// Kernel 1: gather X[inv] -> fp16 mma 3x3 conv -> relu -> atomic seg-sum
// grid (625, 3), block 256 (8 warps), PERSISTENT over 5 tiles each.
// Weights/bias loaded once per CTA (coalesced); pad slots zeroed once.
// Per tile: quad-cooperative gather -> sync -> 36 HMMA/warp -> sync -> red.v4.
// ---------------------------------------------------------------------------
__global__ void __launch_bounds__(T1)
pre_conv_mma_kernel(const float* __restrict__ X, const int* __restrict__ inv,
                    const int* __restrict__ index)
{
    __shared__ uint32_t xs[XS_WORDS];
    __shared__ uint32_t wb[WB_WORDS];
    __shared__ float    bs[16];

    const int tid  = threadIdx.x;
    const int wid  = tid >> 5;
    const int lane = tid & 31;
    const int q    = lane & 3;    // fragment k-quad / D col group
    const int lr   = lane >> 2;   // fragment row / B n index (0..7)
    const int d    = blockIdx.y;

    // One-time: coalesced weight/bias load + pad-slot zeroing
    {
        const uint4* src = reinterpret_cast<const uint4*>(g_wb + d * WB_WORDS);
        uint4* dst = reinterpret_cast<uint4*>(wb);
        for (int i = tid; i < WB_WORDS / 4; i += T1) dst[i] = src[i];
        if (tid < FOUT) bs[tid] = g_bs[d * FOUT + tid];
        // w-pad slots (wslot 0 and 9): never written by gather
        for (int i = tid; i < 34 * 16; i += T1) {
            const int pt = i >> 4, rem = i & 15;
            const int wslot = (rem < 8) ? 0 : 9;
            xs[(pt * 10 + wslot) * 8 + (rem & 7)] = 0u;
        }
    }

    const float bq0 = (tid < T1) ? 0.f : 0.f;  // placeholder keeps regs tight
    (void)bq0;

#pragma unroll 1
    for (int t = 0; t < TPC; ++t) {
        const int tile   = blockIdx.x + NBX * t;
        const int bstart = tile * PN;

        // Edge tiles: zero the pt-halo rows the gather will skip
        if (tile == 0) {
            for (int i = tid; i < 64; i += T1) xs[(0 * 10 + 8) * 8 - 64 + 64 + ((i>>3)+1)*8 - 8 + (i&7)] = 0u;
            // simpler: zero pt row 0, wslots 1..8
            for (int i = tid; i < 64; i += T1)
                xs[(0 * 10 + ((i >> 3) + 1)) * 8 + (i & 7)] = 0u;
        }
        if (tile == NTILE - 1) {
            for (int i = tid; i < 64; i += T1)
                xs[(33 * 10 + ((i >> 3) + 1)) * 8 + (i & 7)] = 0u;
        }
        __syncthreads();   // also orders vs previous tile's mainloop reads

        // Quad-cooperative gather: 272 rows x 4 quarters = 1088 lane tasks
        for (int i = tid; i < 34 * 8 * 4; i += T1) {
            const int r  = i >> 2;          // row 0..271
            const int tq = i & 3;           // 16B quarter
            const int pt = r >> 3;
            const int w  = r & 7;
            const int gp = bstart - 1 + pt;
            if ((unsigned)gp >= NPTS) continue;
            const int idx = inv[(d * NPTS + gp) * BW + w];
            const float4 v = reinterpret_cast<const float4*>(X)[idx * 4 + tq];
            const int woff = (pt * 10 + w + 1) * 8 + 4 * (tq & 1) + (tq >> 1);
            xs[woff]     = pack_f16x2(v.x, v.y);
            xs[woff + 2] = pack_f16x2(v.z, v.w);
        }
        __syncthreads();

        // A-fragment bases: m-tile mt covers rows wid*32 + mt*16 + {lr, lr+8}
        int base_lo[2], base_hi[2];
#pragma unroll
        for (int mt = 0; mt < 2; ++mt) {
            const int ptl = wid * 4 + mt * 2;
            base_lo[mt] = (ptl * 10 + lr) * 8 + 2 * q;
            base_hi[mt] = base_lo[mt] + 80;
        }

        float acc[2][2][4];
#pragma unroll
        for (int mt = 0; mt < 2; ++mt)
#pragma unroll
            for (int nt = 0; nt < 2; ++nt)
#pragma unroll
                for (int i = 0; i < 4; ++i) acc[mt][nt][i] = 0.f;

#pragma unroll
        for (int a = 0; a < 3; ++a) {
#pragma unroll
            for (int b = 0; b < 3; ++b) {
                const int tap  = a * 3 + b;
                const int toff = (a * 10 + b) * 8;
                const uint2 bf0 = *reinterpret_cast<const uint2*>(
                    wb + (tap * 16 + lr) * 8 + 2 * q);
                const uint2 bf1 = *reinterpret_cast<const uint2*>(
                    wb + (tap * 16 + 8 + lr) * 8 + 2 * q);
#pragma unroll
                for (int mt = 0; mt < 2; ++mt) {
                    const uint2 alo = *reinterpret_cast<const uint2*>(
                        xs + base_lo[mt] + toff);
                    const uint2 ahi = *reinterpret_cast<const uint2*>(
                        xs + base_hi[mt] + toff);
                    MMA_F16(acc[mt][0], alo.x, ahi.x, alo.y, ahi.y, bf0.x, bf0.y);
                    MMA_F16(acc[mt][1], alo.x, ahi.x, alo.y, ahi.y, bf1.x, bf1.y);
                }
            }
        }
        __syncthreads();   // xs reads done; next tile may overwrite

        // Epilogue: bias + relu + ONE red.v4 per (mt, half); filters [4q,4q+4)
        const float b0v = bs[4 * q + 0], b1v = bs[4 * q + 1];
        const float b2v = bs[4 * q + 2], b3v = bs[4 * q + 3];
#pragma unroll
        for (int mt = 0; mt < 2; ++mt) {
            const int ptl   = wid * 4 + mt * 2;
            const int seg_l = index[d * NPTS + bstart + ptl];
            const int seg_h = index[d * NPTS + bstart + ptl + 1];
            float* base_l = g_seg + ((d * NSEG + seg_l) * BW + lr) * FOUT + 4 * q;
            float* base_h = g_seg + ((d * NSEG + seg_h) * BW + lr) * FOUT + 4 * q;
            {
                const float v0 = fmaxf(acc[mt][0][0] + b0v, 0.f);
                const float v1 = fmaxf(acc[mt][0][1] + b1v, 0.f);
                const float v2 = fmaxf(acc[mt][1][0] + b2v, 0.f);
                const float v3 = fmaxf(acc[mt][1][1] + b3v, 0.f);
                asm volatile("red.global.add.v4.f32 [%0], {%1,%2,%3,%4};"
                             :: "l"(base_l), "f"(v0), "f"(v1), "f"(v2), "f"(v3)
                             : "memory");
            }
            {
                const float v0 = fmaxf(acc[mt][0][2] + b0v, 0.f);
                const float v1 = fmaxf(acc[mt][0][3] + b1v, 0.f);
                const float v2 = fmaxf(acc[mt][1][2] + b2v, 0.f);
                const float v3 = fmaxf(acc[mt][1][3] + b3v, 0.f);
                asm volatile("red.global.add.v4.f32 [%0], {%1,%2,%3,%4};"
                             :: "l"(base_h), "f"(v0), "f"(v1), "f"(v2), "f"(v3)
                             : "memory");
            }
        }
    }
}

// ---------------------------------------------------------------------------
// Kernel 2: post conv (3,1) + relu on g_seg -> g_z
// ---------------------------------------------------------------------------
__global__ void __launch_bounds__(256)
post_conv_kernel(const float* __restrict__ post_w, const float* __restrict__ post_b)
{
    __shared__ float ws[768];
    __shared__ float bs[16];
    const int tid = threadIdx.x;
    const int d   = blockIdx.y;
    for (int i = tid; i < 768; i += 256) ws[i] = post_w[d * 768 + i];
    if (tid < FOUT) bs[tid] = post_b[d * FOUT + tid];
    __syncthreads();

    const int gt = blockIdx.x * 256 + tid;
    const int s  = gt >> 3;
    const int w  = gt & 7;

    float acc[16];
#pragma unroll
    for (int f = 0; f < 16; ++f) acc[f] = 0.f;

#pragma unroll
    for (int a = 0; a < 3; ++a) {
        const int ss = s + a - 1;
        if (ss < 0 || ss >= NSEG) continue;
        const float4* src = reinterpret_cast<const float4*>(
            g_seg + ((d * NSEG + ss) * BW + w) * FOUT);
#pragma unroll
        for (int cg = 0; cg < 4; ++cg) {
            const float4 x4 = src[cg];
            const float* wr = ws + (a * 16 + cg * 4) * 16;
#pragma unroll
            for (int f = 0; f < 16; ++f) acc[f] += x4.x * wr[f];
#pragma unroll
            for (int f = 0; f < 16; ++f) acc[f] += x4.y * wr[16 + f];
#pragma unroll
            for (int f = 0; f < 16; ++f) acc[f] += x4.z * wr[32 + f];
#pragma unroll
            for (int f = 0; f < 16; ++f) acc[f] += x4.w * wr[48 + f];
        }
    }

    float4* dst = reinterpret_cast<float4*>(g_z + ((d * NSEG + s) * BW + w) * FOUT);
#pragma unroll
    for (int fg = 0; fg < 4; ++fg) {
        float4 v;
        v.x = fmaxf(acc[fg * 4 + 0] + bs[fg * 4 + 0], 0.f);
        v.y = fmaxf(acc[fg * 4 + 1] + bs[fg * 4 + 1], 0.f);
        v.z = fmaxf(acc[fg * 4 + 2] + bs[fg * 4 + 2], 0.f);
        v.w = fmaxf(acc[fg * 4 + 3] + bs[fg * 4 + 3], 0.f);
        dst[fg] = v;
    }
}

// ---------------------------------------------------------------------------
// Kernel 3: Y[n,w,:] = sum_d g_z[d, index[d,n], w, :]
// Each thread: two n's (n, n+NPTS/2) -> 6 independent L2 loads in flight.
// ---------------------------------------------------------------------------
__global__ void __launch_bounds__(256)
gather_out_kernel(const int* __restrict__ index, float* __restrict__ out)
{
    const int gt = blockIdx.x * 256 + threadIdx.x;   // 0 .. NPTS*BW*2-1
    if (gt >= NPTS * BW * 2) return;
    const int n   = gt >> 5;          // point in [0, NPTS/2)
    const int rem = gt & 31;
    const int n2  = n + NPTS / 2;

    const int s0 = index[n],            t0 = index[n2];
    const int s1 = index[NPTS + n],     t1 = index[NPTS + n2];
    const int s2 = index[2 * NPTS + n], t2 = index[2 * NPTS + n2];

    const float4 a0 = reinterpret_cast<const float4*>(
        g_z + (size_t)s0 * (BW * FOUT))[rem];
    const float4 a1 = reinterpret_cast<const float4*>(
        g_z + (size_t)(NSEG + s1) * (BW * FOUT))[rem];
    const float4 a2 = reinterpret_cast<const float4*>(
        g_z + (size_t)(2 * NSEG + s2) * (BW * FOUT))[rem];
    const float4 c0 = reinterpret_cast<const float4*>(
        g_z + (size_t)t0 * (BW * FOUT))[rem];
    const float4 c1 = reinterpret_cast<const float4*>(
        g_z + (size_t)(NSEG + t1) * (BW * FOUT))[rem];
    const float4 c2 = reinterpret_cast<const float4*>(
        g_z + (size_t)(2 * NSEG + t2) * (BW * FOUT))[rem];

    float4 r;
    r.x = a0.x + a1.x + a2.x; r.y = a0.y + a1.y + a2.y;
    r.z = a0.z + a1.z + a2.z; r.w = a0.w + a1.w + a2.w;
    reinterpret_cast<float4*>(out)[n * 32 + rem] = r;

    float4 r2;
    r2.x = c0.x + c1.x + c2.x; r2.y = c0.y + c1.y + c2.y;
    r2.z = c0.z + c1.z + c2.z; r2.w = c0.w + c1.w + c2.w;
    reinterpret_cast<float4*>(out)[n2 * 32 + rem] = r2;
}

// ---------------------------------------------------------------------------
extern "C" void kernel_launch(void* const* d_in, const int* in_sizes, int n_in,
                              void* d_out, int out_size)
{
    const float* X      = (const float*)d_in[0];
    const int*   inv    = (const int*)  d_in[1];
    const int*   index  = (const int*)  d_in[2];
    const float* pre_w  = (const float*)d_in[3];
    const float* pre_b  = (const float*)d_in[4];
    const float* post_w = (const float*)d_in[5];
    const float* post_b = (const float*)d_in[6];
    float*       out    = (float*)      d_out;

    zero_seg_kernel<<<2048, 256>>>();
    weight_setup_kernel<<<16, 256>>>(pre_w, pre_b);

    dim3 g1(NBX, NDIM);
    pre_conv_mma_kernel<<<g1, T1>>>(X, inv, index);

    dim3 g2(NSEG * BW / 256, NDIM);
    post_conv_kernel<<<g2, 256>>>(post_w, post_b);

    gather_out_kernel<<<(NPTS * BW * 2 + 255) / 256, 256>>>(index, out);
}